// round 1
// baseline (speedup 1.0000x reference)
#include <cuda_runtime.h>

#define CC 8
#define NN 4096
#define NC (CC*NN)
#define KH 11
#define MAXDET 100

// ---------------- scratch (device globals; no allocation) ----------------
__device__ int    g_m[CC];           // valid count per class
__device__ int    g_vidx[NC];        // compacted valid anchor indices per class
__device__ float4 g_vbox[NC];        // compacted valid boxes per class
__device__ int    g_maxcol[NC];      // per (c,i): first valid overlapping j, -1 if invalid
__device__ float  g_val[NC];         // per (c,i): (1-iou(r,i))*conf[i]
__device__ int    g_candcnt[NC];     // candidates per row
__device__ int    g_candoff[NC];     // CSR offsets
__device__ int    g_cursor[NC];      // scatter cursors
__device__ float  g_cval[NC];        // CSR candidate values
__device__ int    g_cidx[NC];        // CSR candidate anchor idx
__device__ float  g_pavg[NC*12];
__device__ float  g_bavg[NC*4];
__device__ int    g_surv[NC];

// ---------------- IoU exactly as reference ----------------
__device__ __forceinline__ float iou_ref(float4 a, float4 b) {
    float x1 = fmaxf(a.x, b.x);
    float y1 = fmaxf(a.y, b.y);
    float x2 = fminf(a.z, b.z);
    float y2 = fminf(a.w, b.w);
    float w = x2 - x1 + 1.0f;
    float h = y2 - y1 + 1.0f;
    float inter = w * h;
    float areaA = (a.z - a.x + 1.0f) * (a.w - a.y + 1.0f);
    float areaB = (b.z - b.x + 1.0f) * (b.w - b.y + 1.0f);
    float den = areaA + areaB - inter;
    float ov = (den == 0.0f) ? 0.0f : inter / den;
    return (w <= 0.0f || h <= 0.0f) ? 0.0f : ov;
}

// ---------------- K0: per-class compaction of valid anchors ----------------
__global__ __launch_bounds__(1024) void k0_compact(const float* __restrict__ cls,
                                                   const float* __restrict__ boxes) {
    int c = blockIdx.x;
    int t = threadIdx.x;
    __shared__ int scn[1024];
    int a0 = t * 4;
    int flags[4];
    int cnt = 0;
#pragma unroll
    for (int u = 0; u < 4; u++) {
        int a = a0 + u;
        flags[u] = (cls[a * CC + c] > 0.5f) ? 1 : 0;
        cnt += flags[u];
        g_candcnt[c * NN + a] = 0;
        g_cursor[c * NN + a] = 0;
    }
    scn[t] = cnt;
    __syncthreads();
    for (int off = 1; off < 1024; off <<= 1) {
        int v = (t >= off) ? scn[t - off] : 0;
        __syncthreads();
        scn[t] += v;
        __syncthreads();
    }
    int pos = scn[t] - cnt;
#pragma unroll
    for (int u = 0; u < 4; u++) {
        int a = a0 + u;
        if (flags[u]) {
            g_vidx[c * NN + pos] = a;
            const float* bp = boxes + (size_t)a * (CC * 4) + c * 4;
            g_vbox[c * NN + pos] = make_float4(bp[0], bp[1], bp[2], bp[3]);
            pos++;
        }
    }
    if (t == 1023) g_m[c] = scn[1023];
}

// ---------------- K1: first-overlap scan (max_col) + candidate value ----------------
__global__ __launch_bounds__(256) void k1_maxcol(const float* __restrict__ cls,
                                                 const float* __restrict__ boxes,
                                                 const float* __restrict__ conf) {
    extern __shared__ unsigned char s1[];
    float4* sbox = (float4*)s1;
    int* sidx = (int*)(sbox + NN);

    int c = blockIdx.x >> 4;
    int ib = (blockIdx.x & 15) * 256;
    int m = g_m[c];
    for (int k = threadIdx.x; k < m; k += 256) {
        sbox[k] = g_vbox[c * NN + k];
        sidx[k] = g_vidx[c * NN + k];
    }
    __syncthreads();

    int i = ib + threadIdx.x;
    float sc = cls[i * CC + c];
    if (sc > 0.5f) {
        const float* bp = boxes + (size_t)i * (CC * 4) + c * 4;
        float4 bi = make_float4(bp[0], bp[1], bp[2], bp[3]);
        int r = -1;
        float ovr = 0.0f;
        for (int k = 0; k < m; k++) {
            int j = sidx[k];
            if (j > i) break;               // i itself is in the list -> guaranteed hit earlier
            float ov = iou_ref(bi, sbox[k]);
            if (ov > 0.5f) { r = j; ovr = ov; break; }
        }
        g_maxcol[c * NN + i] = r;
        float v = (1.0f - ovr) * conf[i * CC + c];
        g_val[c * NN + i] = v;
        if (r >= 0 && v != 0.0f) atomicAdd(&g_candcnt[c * NN + r], 1);
    } else {
        g_maxcol[c * NN + i] = -1;
        g_val[c * NN + i] = 0.0f;
    }
}

// ---------------- K2: exclusive prefix sum over 32768 counts ----------------
__global__ __launch_bounds__(1024) void k2_prefix() {
    __shared__ int scn[1024];
    int t = threadIdx.x;
    int base = t * 32;
    int loc[32];
    int sum = 0;
#pragma unroll
    for (int u = 0; u < 32; u++) {
        loc[u] = sum;
        sum += g_candcnt[base + u];
    }
    scn[t] = sum;
    __syncthreads();
    for (int off = 1; off < 1024; off <<= 1) {
        int v = (t >= off) ? scn[t - off] : 0;
        __syncthreads();
        scn[t] += v;
        __syncthreads();
    }
    int tb = scn[t] - sum;
#pragma unroll
    for (int u = 0; u < 32; u++) g_candoff[base + u] = tb + loc[u];
}

// ---------------- K3: scatter candidates into CSR ----------------
__global__ __launch_bounds__(1024) void k3_scatter() {
    int f = blockIdx.x * 1024 + threadIdx.x;
    int r = g_maxcol[f];
    float v = g_val[f];
    if (r >= 0 && v != 0.0f) {
        int c = f >> 12;
        int row = c * NN + r;
        int pos = atomicAdd(&g_cursor[row], 1);
        int o = g_candoff[row] + pos;
        g_cval[o] = v;
        g_cidx[o] = f & (NN - 1);
    }
}

// ---------------- K4: per-row top-11 (lexicographic) + averages ----------------
__global__ __launch_bounds__(1024) void k4_select(const float* __restrict__ poses,
                                                  const float* __restrict__ boxes) {
    int row = blockIdx.x * 1024 + threadIdx.x;
    int c = row >> 12;
    int cnt = g_candcnt[row];
    int off = g_candoff[row];

    float bv[KH];
    int bid[KH];
    int ns = 0;
    for (int q = 0; q < cnt; q++) {
        float v = g_cval[off + q];
        int id = g_cidx[off + q];
        bool ins;
        if (ns < KH) ins = true;
        else {
            float lv = bv[KH - 1]; int li = bid[KH - 1];
            ins = (v < lv) || (v == lv && id < li);
        }
        if (ins) {
            int p = (ns < KH) ? ns : (KH - 1);
            while (p > 0) {
                float pv = bv[p - 1]; int pi = bid[p - 1];
                if (v < pv || (v == pv && id < pi)) { bv[p] = pv; bid[p] = pi; p--; }
                else break;
            }
            bv[p] = v; bid[p] = id;
            if (ns < KH) ns++;
        }
    }

    int L = min(KH, g_m[c]);
    int used = min(ns, L);
    float ps[12];
    float bs4[4];
#pragma unroll
    for (int d = 0; d < 12; d++) ps[d] = 0.0f;
#pragma unroll
    for (int d = 0; d < 4; d++) bs4[d] = 0.0f;
    for (int q = 0; q < used; q++) {
        int a = bid[q];
        const float* pp = poses + (size_t)a * (CC * 12) + c * 12;
#pragma unroll
        for (int d = 0; d < 12; d++) ps[d] += pp[d];
        const float* bp = boxes + (size_t)a * (CC * 4) + c * 4;
#pragma unroll
        for (int d = 0; d < 4; d++) bs4[d] += bp[d];
    }
    int sv = (used > 0) ? 1 : 0;
    float den = (float)used;
    g_surv[row] = sv;
#pragma unroll
    for (int d = 0; d < 12; d++) g_pavg[row * 12 + d] = sv ? (ps[d] / den) : 0.0f;
#pragma unroll
    for (int d = 0; d < 4; d++) g_bavg[row * 4 + d] = sv ? (bs4[d] / den) : 0.0f;
}

// ---------------- K5: global selection + output assembly ----------------
__global__ __launch_bounds__(1024) void k5_final(const float* __restrict__ cls,
                                                 float* __restrict__ out, int out_size) {
    __shared__ int scn[1024];
    __shared__ int hist[2048];
    __shared__ int sel[MAXDET];
    __shared__ unsigned arr[MAXDET];
    __shared__ unsigned srt[MAXDET];
    __shared__ int S_sh, b1_sh, t1_sh, b2_sh, t2_sh, e_sh, gcnt, ecnt;
    __shared__ unsigned K100_sh;

    int t = threadIdx.x;
    unsigned keys[32];
    int cnt = 0;
    int base = t * 32;
#pragma unroll
    for (int u = 0; u < 32; u++) {
        int f = base + u;
        unsigned k = 0u;
        if (g_surv[f]) {
            int c = f >> 12, a = f & (NN - 1);
            unsigned ub = __float_as_uint(cls[a * CC + c]);
            k = ub ^ ((ub & 0x80000000u) ? 0xFFFFFFFFu : 0x80000000u);
            cnt++;
        }
        keys[u] = k;
    }
    scn[t] = cnt;
    if (t == 0) { gcnt = 0; ecnt = 0; }
    __syncthreads();
    for (int off = 1; off < 1024; off <<= 1) {
        int v = (t >= off) ? scn[t - off] : 0;
        __syncthreads();
        scn[t] += v;
        __syncthreads();
    }
    int rank = scn[t] - cnt;
    if (cnt > 0 && rank < MAXDET) {
#pragma unroll
        for (int u = 0; u < 32; u++) {
            int f = base + u;
            if (g_surv[f]) {
                if (rank < MAXDET) sel[rank] = f;
                rank++;
            }
        }
    }
    if (t == 1023) S_sh = scn[1023];

    // ---- radix-select level 1 (top 11 bits) ----
    hist[t] = 0; hist[t + 1024] = 0;
    __syncthreads();
#pragma unroll
    for (int u = 0; u < 32; u++) atomicAdd(&hist[keys[u] >> 21], 1);
    __syncthreads();
    if (t == 0) {
        int cum = 0, b;
        for (b = 2047; b >= 0; b--) { cum += hist[b]; if (cum >= MAXDET) break; }
        b1_sh = b;
        t1_sh = MAXDET - (cum - hist[b]);
    }
    __syncthreads();
    unsigned b1 = (unsigned)b1_sh;

    // ---- level 2 (next 11 bits) ----
    hist[t] = 0; hist[t + 1024] = 0;
    __syncthreads();
#pragma unroll
    for (int u = 0; u < 32; u++)
        if ((keys[u] >> 21) == b1) atomicAdd(&hist[(keys[u] >> 10) & 2047u], 1);
    __syncthreads();
    if (t == 0) {
        int tgt = t1_sh, cum = 0, b;
        for (b = 2047; b >= 0; b--) { cum += hist[b]; if (cum >= tgt) break; }
        b2_sh = b;
        t2_sh = tgt - (cum - hist[b]);
    }
    __syncthreads();
    unsigned pre = (b1 << 11) | (unsigned)b2_sh;

    // ---- level 3 (low 10 bits) ----
    hist[t] = 0; hist[t + 1024] = 0;
    __syncthreads();
#pragma unroll
    for (int u = 0; u < 32; u++)
        if ((keys[u] >> 10) == pre) atomicAdd(&hist[keys[u] & 1023u], 1);
    __syncthreads();
    if (t == 0) {
        int tgt = t2_sh, cum = 0, b;
        for (b = 1023; b >= 0; b--) { cum += hist[b]; if (cum >= tgt) break; }
        K100_sh = (pre << 10) | (unsigned)b;
        e_sh = tgt - (cum - hist[b]);
    }
    __syncthreads();
    unsigned K100 = K100_sh;
    int e = e_sh;
    int g = MAXDET - e;

    // ---- collect exactly 100 keys ----
#pragma unroll
    for (int u = 0; u < 32; u++) {
        unsigned k = keys[u];
        if (k > K100) {
            int p = atomicAdd(&gcnt, 1);
            arr[p] = k;
        } else if (k == K100) {
            int p = atomicAdd(&ecnt, 1);
            if (p < e) arr[g + p] = k;
        }
    }
    __syncthreads();

    // ---- rank sort 100 keys descending ----
    if (t < MAXDET) {
        unsigned kt = arr[t];
        int r = 0;
        for (int j = 0; j < MAXDET; j++) {
            unsigned kj = arr[j];
            r += ((kj > kt) || (kj == kt && j < t)) ? 1 : 0;
        }
        srt[r] = kt;
    }
    __syncthreads();

    int S = S_sh;
    // outputs: [scores 100][labels 100][poses 1200][idx 100][boxes 400] = 1900 floats
    for (int q = t; q < MAXDET; q += 1024) {
        float osc = -1.0f;
        if (q < S) {
            unsigned u = srt[q];
            u = (u & 0x80000000u) ? (u ^ 0x80000000u) : ~u;
            osc = __uint_as_float(u);
        }
        if (q < out_size) out[q] = osc;
        float lab = (q < S) ? (float)(sel[q] >> 12) : -1.0f;
        if (100 + q < out_size) out[100 + q] = lab;
        float idx = (q < S) ? (float)(sel[q] & (NN - 1)) : -1.0f;
        if (1400 + q < out_size) out[1400 + q] = idx;
    }
    for (int q = t; q < 1200; q += 1024) {
        int k = q / 12, d = q % 12;
        float v = (k < S) ? g_pavg[sel[k] * 12 + d] : -1.0f;
        if (200 + q < out_size) out[200 + q] = v;
    }
    for (int q = t; q < 400; q += 1024) {
        int k = q >> 2, d = q & 3;
        float v = (k < S) ? g_bavg[sel[k] * 4 + d] : -1.0f;
        if (1500 + q < out_size) out[1500 + q] = v;
    }
}

// ---------------- launcher ----------------
extern "C" void kernel_launch(void* const* d_in, const int* in_sizes, int n_in,
                              void* d_out, int out_size) {
    (void)in_sizes; (void)n_in;
    const float* boxes = (const float*)d_in[1];
    const float* cls   = (const float*)d_in[2];
    const float* poses = (const float*)d_in[3];
    const float* conf  = (const float*)d_in[4];
    float* out = (float*)d_out;

    size_t smem1 = (size_t)NN * sizeof(float4) + (size_t)NN * sizeof(int); // 80KB
    cudaFuncSetAttribute(k1_maxcol, cudaFuncAttributeMaxDynamicSharedMemorySize, (int)smem1);

    k0_compact<<<CC, 1024>>>(cls, boxes);
    k1_maxcol<<<CC * 16, 256, smem1>>>(cls, boxes, conf);
    k2_prefix<<<1, 1024>>>();
    k3_scatter<<<NC / 1024, 1024>>>();
    k4_select<<<NC / 1024, 1024>>>(poses, boxes);
    k5_final<<<1, 1024>>>(cls, out, out_size);
}

// round 2
// speedup vs baseline: 1.5355x; 1.5355x over previous
#include <cuda_runtime.h>

#define CC 8
#define NN 4096
#define NC (CC*NN)
#define KH 11
#define MAXDET 100

// ---------------- scratch (device globals; no allocation) ----------------
__device__ int    g_m[CC];           // valid count per class
__device__ int    g_vidx[NC];        // compacted valid anchor indices per class
__device__ float4 g_vbox[NC];        // compacted valid boxes per class
__device__ int    g_maxcol[NC];      // per (c,i): first valid overlapping j, -1 if invalid
__device__ float  g_val[NC];         // per (c,i): (1-iou(r,i))*conf[i]
__device__ int    g_candcnt[NC];     // candidates per row
__device__ int    g_candoff[NC];     // CSR offsets
__device__ int    g_cursor[NC];      // scatter cursors
__device__ unsigned long long g_cand[NC]; // CSR candidates: (valbits<<32)|anchor
__device__ float  g_pavg[NC*12];
__device__ float  g_bavg[NC*4];
__device__ int    g_surv[NC];

// ---------------- K0: per-class compaction of valid anchors ----------------
__global__ __launch_bounds__(1024) void k0_compact(const float* __restrict__ cls,
                                                   const float* __restrict__ boxes) {
    int c = blockIdx.x;
    int t = threadIdx.x;
    __shared__ int scn[1024];
    int a0 = t * 4;
    int flags[4];
    int cnt = 0;
#pragma unroll
    for (int u = 0; u < 4; u++) {
        int a = a0 + u;
        flags[u] = (cls[a * CC + c] > 0.5f) ? 1 : 0;
        cnt += flags[u];
        g_candcnt[c * NN + a] = 0;
        g_cursor[c * NN + a] = 0;
    }
    scn[t] = cnt;
    __syncthreads();
    for (int off = 1; off < 1024; off <<= 1) {
        int v = (t >= off) ? scn[t - off] : 0;
        __syncthreads();
        scn[t] += v;
        __syncthreads();
    }
    int pos = scn[t] - cnt;
#pragma unroll
    for (int u = 0; u < 4; u++) {
        int a = a0 + u;
        if (flags[u]) {
            g_vidx[c * NN + pos] = a;
            const float* bp = boxes + (size_t)a * (CC * 4) + c * 4;
            g_vbox[c * NN + pos] = make_float4(bp[0], bp[1], bp[2], bp[3]);
            pos++;
        }
    }
    if (t == 1023) g_m[c] = scn[1023];
}

// ---------------- K1: warp-cooperative first-overlap scan ----------------
__global__ __launch_bounds__(256) void k1_maxcol(const float* __restrict__ cls,
                                                 const float* __restrict__ boxes,
                                                 const float* __restrict__ conf) {
    extern __shared__ unsigned char s1[];
    float4* sbox  = (float4*)s1;                 // [NN]
    float*  sarea = (float*)(sbox + NN);         // [NN]
    int*    sidx  = (int*)(sarea + NN);          // [NN]

    int c  = blockIdx.x >> 4;
    int ib = (blockIdx.x & 15) * 256;
    int m  = g_m[c];
    for (int k = threadIdx.x; k < m; k += 256) {
        float4 b = g_vbox[c * NN + k];
        sbox[k]  = b;
        sarea[k] = (b.z - b.x + 1.0f) * (b.w - b.y + 1.0f);
        sidx[k]  = g_vidx[c * NN + k];
    }
    __syncthreads();

    const unsigned FULL = 0xFFFFFFFFu;
    int lane = threadIdx.x & 31;
    int base = ib + (threadIdx.x & ~31);   // first anchor of this warp's 32
    int il   = base + lane;

    float sc = cls[il * CC + c];
    const float* bp = boxes + (size_t)il * (CC * 4) + c * 4;
    float4 bl = make_float4(bp[0], bp[1], bp[2], bp[3]);
    float cf  = conf[il * CC + c];
    bool validl = sc > 0.5f;

    int   myR = -1;
    float myV = 0.0f;

    unsigned vm = __ballot_sync(FULL, validl);
    while (vm) {
        int a = __ffs(vm) - 1;
        vm &= vm - 1;
        float ax = __shfl_sync(FULL, bl.x, a);
        float ay = __shfl_sync(FULL, bl.y, a);
        float az = __shfl_sync(FULL, bl.z, a);
        float aw = __shfl_sync(FULL, bl.w, a);
        float areaA = (az - ax + 1.0f) * (aw - ay + 1.0f);

        int r = -1;
        float ov = 0.0f;
        for (int k0 = 0; k0 < m; k0 += 32) {
            int k = k0 + lane;
            bool hit = false;
            float inter = 0.0f, den = 1.0f;
            if (k < m) {
                float4 bb = sbox[k];
                float x1 = fmaxf(ax, bb.x);
                float y1 = fmaxf(ay, bb.y);
                float x2 = fminf(az, bb.z);
                float y2 = fminf(aw, bb.w);
                float w = x2 - x1 + 1.0f;
                float h = y2 - y1 + 1.0f;
                inter = w * h;
                den   = areaA + sarea[k] - inter;
                hit   = (w > 0.0f) && (h > 0.0f) && (inter > 0.5f * den);
            }
            unsigned hb = __ballot_sync(FULL, hit);
            if (hb) {
                int fl = __ffs(hb) - 1;
                float in_ = __shfl_sync(FULL, inter, fl);
                float dn_ = __shfl_sync(FULL, den, fl);
                ov = in_ / dn_;          // exact reference value, one div per anchor
                r  = sidx[k0 + fl];
                break;
            }
        }
        if (lane == a) { myR = r; myV = (1.0f - ov) * cf; }
    }

    g_maxcol[c * NN + il] = myR;
    g_val[c * NN + il]    = myV;
    if (myR >= 0 && myV != 0.0f) atomicAdd(&g_candcnt[c * NN + myR], 1);
}

// ---------------- K2: exclusive prefix sum over 32768 counts ----------------
__global__ __launch_bounds__(1024) void k2_prefix() {
    __shared__ int scn[1024];
    int t = threadIdx.x;
    int base = t * 32;
    int loc[32];
    int sum = 0;
#pragma unroll
    for (int u = 0; u < 32; u++) {
        loc[u] = sum;
        sum += g_candcnt[base + u];
    }
    scn[t] = sum;
    __syncthreads();
    for (int off = 1; off < 1024; off <<= 1) {
        int v = (t >= off) ? scn[t - off] : 0;
        __syncthreads();
        scn[t] += v;
        __syncthreads();
    }
    int tb = scn[t] - sum;
#pragma unroll
    for (int u = 0; u < 32; u++) g_candoff[base + u] = tb + loc[u];
}

// ---------------- K3: scatter candidates into CSR ----------------
__global__ __launch_bounds__(256) void k3_scatter() {
    int f = blockIdx.x * 256 + threadIdx.x;
    int r = g_maxcol[f];
    float v = g_val[f];
    if (r >= 0 && v != 0.0f) {
        int c = f >> 12;
        int row = c * NN + r;
        int pos = atomicAdd(&g_cursor[row], 1);
        unsigned long long key =
            ((unsigned long long)__float_as_uint(v) << 32) | (unsigned)(f & (NN - 1));
        g_cand[g_candoff[row] + pos] = key;
    }
}

// ---------------- K4: per-row top-11 (branchless register network) + averages ----------------
__global__ __launch_bounds__(256) void k4_select(const float* __restrict__ poses,
                                                 const float* __restrict__ boxes) {
    int row = blockIdx.x * 256 + threadIdx.x;
    int c   = row >> 12;
    int cnt = g_candcnt[row];
    int off = g_candoff[row];

    unsigned long long b[KH];
#pragma unroll
    for (int p = 0; p < KH; p++) b[p] = ~0ULL;

    for (int q = 0; q < cnt; q++) {
        unsigned long long x = g_cand[off + q];
#pragma unroll
        for (int p = 0; p < KH; p++) {
            unsigned long long lo = (b[p] < x) ? b[p] : x;
            unsigned long long hi = (b[p] < x) ? x : b[p];
            b[p] = lo;
            x = hi;
        }
    }

    int L  = min(KH, g_m[c]);
    int ns = min(cnt, KH);
    int used = min(ns, L);

    float ps[12];
    float bs4[4];
#pragma unroll
    for (int d = 0; d < 12; d++) ps[d] = 0.0f;
#pragma unroll
    for (int d = 0; d < 4; d++) bs4[d] = 0.0f;

    for (int q = 0; q < used; q++) {
        int a = (int)(b[q] & 0xFFFFFFFFu);
        const float* pp = poses + (size_t)a * (CC * 12) + c * 12;
#pragma unroll
        for (int d = 0; d < 12; d++) ps[d] += pp[d];
        const float* bx = boxes + (size_t)a * (CC * 4) + c * 4;
#pragma unroll
        for (int d = 0; d < 4; d++) bs4[d] += bx[d];
    }
    int sv = (used > 0) ? 1 : 0;
    float den = (float)used;
    g_surv[row] = sv;
#pragma unroll
    for (int d = 0; d < 12; d++) g_pavg[row * 12 + d] = sv ? (ps[d] / den) : 0.0f;
#pragma unroll
    for (int d = 0; d < 4; d++) g_bavg[row * 4 + d] = sv ? (bs4[d] / den) : 0.0f;
}

// ---------------- K5: global selection + output assembly ----------------
__global__ __launch_bounds__(1024) void k5_final(const float* __restrict__ cls,
                                                 float* __restrict__ out, int out_size) {
    __shared__ int scn[1024];
    __shared__ int hist[2048];
    __shared__ int sel[MAXDET];
    __shared__ unsigned arr[MAXDET];
    __shared__ unsigned srt[MAXDET];
    __shared__ int S_sh, b1_sh, t1_sh, b2_sh, t2_sh, e_sh, gcnt, ecnt;
    __shared__ unsigned K100_sh;

    int t = threadIdx.x;
    unsigned keys[32];
    int cnt = 0;
    int base = t * 32;
#pragma unroll
    for (int u = 0; u < 32; u++) {
        int f = base + u;
        unsigned k = 0u;
        if (g_surv[f]) {
            int c = f >> 12, a = f & (NN - 1);
            unsigned ub = __float_as_uint(cls[a * CC + c]);
            k = ub ^ ((ub & 0x80000000u) ? 0xFFFFFFFFu : 0x80000000u);
            cnt++;
        }
        keys[u] = k;
    }
    scn[t] = cnt;
    if (t == 0) { gcnt = 0; ecnt = 0; }
    __syncthreads();
    for (int off = 1; off < 1024; off <<= 1) {
        int v = (t >= off) ? scn[t - off] : 0;
        __syncthreads();
        scn[t] += v;
        __syncthreads();
    }
    int rank = scn[t] - cnt;
    if (cnt > 0 && rank < MAXDET) {
#pragma unroll
        for (int u = 0; u < 32; u++) {
            int f = base + u;
            if (g_surv[f]) {
                if (rank < MAXDET) sel[rank] = f;
                rank++;
            }
        }
    }
    if (t == 1023) S_sh = scn[1023];

    // ---- radix-select level 1 (top 11 bits) ----
    hist[t] = 0; hist[t + 1024] = 0;
    __syncthreads();
#pragma unroll
    for (int u = 0; u < 32; u++) atomicAdd(&hist[keys[u] >> 21], 1);
    __syncthreads();
    if (t == 0) {
        int cum = 0, b;
        for (b = 2047; b >= 0; b--) { cum += hist[b]; if (cum >= MAXDET) break; }
        b1_sh = b;
        t1_sh = MAXDET - (cum - hist[b]);
    }
    __syncthreads();
    unsigned b1 = (unsigned)b1_sh;

    // ---- level 2 (next 11 bits) ----
    hist[t] = 0; hist[t + 1024] = 0;
    __syncthreads();
#pragma unroll
    for (int u = 0; u < 32; u++)
        if ((keys[u] >> 21) == b1) atomicAdd(&hist[(keys[u] >> 10) & 2047u], 1);
    __syncthreads();
    if (t == 0) {
        int tgt = t1_sh, cum = 0, b;
        for (b = 2047; b >= 0; b--) { cum += hist[b]; if (cum >= tgt) break; }
        b2_sh = b;
        t2_sh = tgt - (cum - hist[b]);
    }
    __syncthreads();
    unsigned pre = (b1 << 11) | (unsigned)b2_sh;

    // ---- level 3 (low 10 bits) ----
    hist[t] = 0; hist[t + 1024] = 0;
    __syncthreads();
#pragma unroll
    for (int u = 0; u < 32; u++)
        if ((keys[u] >> 10) == pre) atomicAdd(&hist[keys[u] & 1023u], 1);
    __syncthreads();
    if (t == 0) {
        int tgt = t2_sh, cum = 0, b;
        for (b = 1023; b >= 0; b--) { cum += hist[b]; if (cum >= tgt) break; }
        K100_sh = (pre << 10) | (unsigned)b;
        e_sh = tgt - (cum - hist[b]);
    }
    __syncthreads();
    unsigned K100 = K100_sh;
    int e = e_sh;
    int g = MAXDET - e;

    // ---- collect exactly 100 keys ----
#pragma unroll
    for (int u = 0; u < 32; u++) {
        unsigned k = keys[u];
        if (k > K100) {
            int p = atomicAdd(&gcnt, 1);
            arr[p] = k;
        } else if (k == K100) {
            int p = atomicAdd(&ecnt, 1);
            if (p < e) arr[g + p] = k;
        }
    }
    __syncthreads();

    // ---- rank sort 100 keys descending ----
    if (t < MAXDET) {
        unsigned kt = arr[t];
        int r = 0;
        for (int j = 0; j < MAXDET; j++) {
            unsigned kj = arr[j];
            r += ((kj > kt) || (kj == kt && j < t)) ? 1 : 0;
        }
        srt[r] = kt;
    }
    __syncthreads();

    int S = S_sh;
    // outputs: [scores 100][labels 100][poses 1200][idx 100][boxes 400] = 1900 floats
    for (int q = t; q < MAXDET; q += 1024) {
        float osc = -1.0f;
        if (q < S) {
            unsigned u = srt[q];
            u = (u & 0x80000000u) ? (u ^ 0x80000000u) : ~u;
            osc = __uint_as_float(u);
        }
        if (q < out_size) out[q] = osc;
        float lab = (q < S) ? (float)(sel[q] >> 12) : -1.0f;
        if (100 + q < out_size) out[100 + q] = lab;
        float idx = (q < S) ? (float)(sel[q] & (NN - 1)) : -1.0f;
        if (1400 + q < out_size) out[1400 + q] = idx;
    }
    for (int q = t; q < 1200; q += 1024) {
        int k = q / 12, d = q % 12;
        float v = (k < S) ? g_pavg[sel[k] * 12 + d] : -1.0f;
        if (200 + q < out_size) out[200 + q] = v;
    }
    for (int q = t; q < 400; q += 1024) {
        int k = q >> 2, d = q & 3;
        float v = (k < S) ? g_bavg[sel[k] * 4 + d] : -1.0f;
        if (1500 + q < out_size) out[1500 + q] = v;
    }
}

// ---------------- launcher ----------------
extern "C" void kernel_launch(void* const* d_in, const int* in_sizes, int n_in,
                              void* d_out, int out_size) {
    (void)in_sizes; (void)n_in;
    const float* boxes = (const float*)d_in[1];
    const float* cls   = (const float*)d_in[2];
    const float* poses = (const float*)d_in[3];
    const float* conf  = (const float*)d_in[4];
    float* out = (float*)d_out;

    size_t smem1 = (size_t)NN * sizeof(float4) + (size_t)NN * sizeof(float)
                 + (size_t)NN * sizeof(int); // 96KB
    cudaFuncSetAttribute(k1_maxcol, cudaFuncAttributeMaxDynamicSharedMemorySize, (int)smem1);

    k0_compact<<<CC, 1024>>>(cls, boxes);
    k1_maxcol<<<CC * 16, 256, smem1>>>(cls, boxes, conf);
    k2_prefix<<<1, 1024>>>();
    k3_scatter<<<NC / 256, 256>>>();
    k4_select<<<NC / 256, 256>>>(poses, boxes);
    k5_final<<<1, 1024>>>(cls, out, out_size);
}

// round 3
// speedup vs baseline: 1.8642x; 1.2141x over previous
#include <cuda_runtime.h>

#define CC 8
#define NN 4096
#define NC (CC*NN)
#define KH 11
#define MAXDET 100

// ---------------- scratch (device globals; no allocation) ----------------
__device__ int    g_m[CC];            // valid count per class
__device__ int    g_vidx[NC];         // compacted valid anchor indices (by rank)
__device__ float4 g_vbox[NC];         // compacted valid boxes (by rank)
__device__ float4 g_sbox[NC];         // sorted-by-x1 boxes (by slot)
__device__ float2 g_saux[NC];         // sorted aux: (area, orig idx as int bits)
__device__ int    g_rmin[NC];         // per sorted slot: min orig idx of hit (init self)
__device__ int    g_maxcol[NC];       // per slot: winning row r
__device__ float  g_val[NC];          // per slot: candidate value
__device__ int    g_candcnt[NC];      // candidates per row (orig-indexed)
__device__ int    g_candoff[NC];      // CSR offsets
__device__ int    g_cursor[NC];       // scatter cursors
__device__ unsigned long long g_cand[NC]; // CSR candidates: (valbits<<32)|anchor
__device__ float  g_pavg[NC*12];
__device__ float  g_bavg[NC*4];
__device__ int    g_surv[NC];

__device__ __forceinline__ unsigned fkey_asc(float x) {
    unsigned u = __float_as_uint(x);
    return (u & 0x80000000u) ? ~u : (u | 0x80000000u);
}

// ---------------- K0: compact + bitonic sort by x1 + emit sorted arrays ----------------
__global__ __launch_bounds__(1024) void k0_compact_sort(const float* __restrict__ cls,
                                                        const float* __restrict__ boxes) {
    __shared__ unsigned long long skey[4096];
    __shared__ int scn[1024];
    int c = blockIdx.x;
    int t = threadIdx.x;

    // --- phase A: compaction (rank order = anchor order; order irrelevant downstream) ---
    int a0 = t * 4;
    int flags[4];
    int cnt = 0;
#pragma unroll
    for (int u = 0; u < 4; u++) {
        int a = a0 + u;
        flags[u] = (cls[a * CC + c] > 0.5f) ? 1 : 0;
        cnt += flags[u];
        g_candcnt[c * NN + a] = 0;
        g_cursor[c * NN + a] = 0;
    }
    scn[t] = cnt;
    __syncthreads();
    for (int off = 1; off < 1024; off <<= 1) {
        int v = (t >= off) ? scn[t - off] : 0;
        __syncthreads();
        scn[t] += v;
        __syncthreads();
    }
    int pos = scn[t] - cnt;
#pragma unroll
    for (int u = 0; u < 4; u++) {
        int a = a0 + u;
        if (flags[u]) {
            g_vidx[c * NN + pos] = a;
            const float* bp = boxes + (size_t)a * (CC * 4) + c * 4;
            g_vbox[c * NN + pos] = make_float4(bp[0], bp[1], bp[2], bp[3]);
            pos++;
        }
    }
    int m = scn[1023];
    if (t == 1023) g_m[c] = m;
    __syncthreads();

    // --- phase B: build sort keys (x1 ascending | rank), pad with max ---
#pragma unroll
    for (int u = 0; u < 4; u++) {
        int s = t + u * 1024;
        unsigned long long key = ~0ULL;
        if (s < m) {
            float x1 = g_vbox[c * NN + s].x;
            key = ((unsigned long long)fkey_asc(x1) << 32) | (unsigned)s;
        }
        skey[s] = key;
    }
    __syncthreads();

    // --- bitonic sort 4096 ascending ---
    for (int k = 2; k <= 4096; k <<= 1) {
        for (int j = k >> 1; j > 0; j >>= 1) {
#pragma unroll
            for (int e = t; e < 2048; e += 1024) {
                int i = 2 * e - (e & (j - 1));
                int p = i + j;
                bool up = ((i & k) == 0);
                unsigned long long A = skey[i], B = skey[p];
                if ((A > B) == up) { skey[i] = B; skey[p] = A; }
            }
            __syncthreads();
        }
    }

    // --- phase C: gather sorted arrays + init rmin ---
#pragma unroll
    for (int u = 0; u < 4; u++) {
        int s = t + u * 1024;
        if (s < m) {
            int rank = (int)(skey[s] & 0xFFFFFFFFu);
            float4 b = g_vbox[c * NN + rank];
            int orig = g_vidx[c * NN + rank];
            float area = (b.z - b.x + 1.0f) * (b.w - b.y + 1.0f);
            g_sbox[c * NN + s] = b;
            g_saux[c * NN + s] = make_float2(area, __int_as_float(orig));
            g_rmin[c * NN + s] = orig;   // self hit (IoU=1) baseline
        }
    }
}

// ---------------- K1: symmetric forward pair scan (sorted by x1) ----------------
#define K1_TILE 128
#define K1_SPAN 1024
__global__ __launch_bounds__(K1_TILE) void k1_pairs() {
    __shared__ float4 tb[K1_SPAN];
    __shared__ float2 ta[K1_SPAN];

    int c  = blockIdx.x >> 5;
    int S0 = (blockIdx.x & 31) * K1_TILE;
    int m  = g_m[c];
    if (S0 >= m) return;

    for (int k = threadIdx.x; k < K1_SPAN; k += K1_TILE) {
        int s = S0 + k;
        if (s < m) {
            tb[k] = g_sbox[c * NN + s];
            ta[k] = g_saux[c * NN + s];
        } else {
            tb[k] = make_float4(3.0e38f, 0.0f, -10.0f, -10.0f); // x1=+inf sentinel
            ta[k] = make_float2(1.0f, __int_as_float(0));
        }
    }
    __syncthreads();

    int s = S0 + threadIdx.x;
    if (s >= m) return;

    float4 a    = tb[threadIdx.x];
    float areaA = ta[threadIdx.x].x;
    int   origI = __float_as_int(ta[threadIdx.x].y);
    float limit = a.z + 1.0f;   // scan while x1_t < x2_s + 1

    int ts = threadIdx.x + 1;
    while (true) {
        float4 b; float2 ax;
        if (ts < K1_SPAN) {
            b  = tb[ts];
            ax = ta[ts];
        } else {
            int gs = S0 + ts;
            if (gs >= m) break;
            b  = g_sbox[c * NN + gs];
            ax = g_saux[c * NN + gs];
        }
        if (b.x >= limit) break;

        float x1 = fmaxf(a.x, b.x);
        float y1 = fmaxf(a.y, b.y);
        float x2 = fminf(a.z, b.z);
        float y2 = fminf(a.w, b.w);
        float w = x2 - x1 + 1.0f;
        float h = y2 - y1 + 1.0f;
        float inter = w * h;
        float den = areaA + ax.x - inter;
        if (w > 0.0f && h > 0.0f && inter > 0.5f * den) {
            int origJ = __float_as_int(ax.y);
            atomicMin(&g_rmin[c * NN + s], origJ);
            atomicMin(&g_rmin[c * NN + S0 + ts], origI);
        }
        ts++;
    }
}

// ---------------- K1b: per-anchor winner -> exact value + row counts ----------------
__global__ __launch_bounds__(256) void k1b_values(const float* __restrict__ boxes,
                                                  const float* __restrict__ conf) {
    int c = blockIdx.x >> 4;
    int s = (blockIdx.x & 15) * 256 + threadIdx.x;
    int m = g_m[c];
    if (s >= m) return;

    int slot = c * NN + s;
    int r    = g_rmin[slot];
    int i    = __float_as_int(g_saux[slot].y);

    float v = 0.0f;
    if (r != i) {
        float4 bi = g_sbox[slot];
        const float* bp = boxes + (size_t)r * (CC * 4) + c * 4;
        float4 br = make_float4(bp[0], bp[1], bp[2], bp[3]);
        float x1 = fmaxf(bi.x, br.x);
        float y1 = fmaxf(bi.y, br.y);
        float x2 = fminf(bi.z, br.z);
        float y2 = fminf(bi.w, br.w);
        float w = x2 - x1 + 1.0f;
        float h = y2 - y1 + 1.0f;
        float inter = w * h;
        float areaI = (bi.z - bi.x + 1.0f) * (bi.w - bi.y + 1.0f);
        float areaR = (br.z - br.x + 1.0f) * (br.w - br.y + 1.0f);
        float den = areaI + areaR - inter;
        float ov = (den == 0.0f) ? 0.0f : inter / den;
        if (w <= 0.0f || h <= 0.0f) ov = 0.0f;
        v = (1.0f - ov) * conf[i * CC + c];
    }
    g_maxcol[slot] = r;
    g_val[slot]    = v;
    if (r != i && v != 0.0f) atomicAdd(&g_candcnt[c * NN + r], 1);
}

// ---------------- K2: exclusive prefix sum over 32768 counts ----------------
__global__ __launch_bounds__(1024) void k2_prefix() {
    __shared__ int scn[1024];
    int t = threadIdx.x;
    int base = t * 32;
    int loc[32];
    int sum = 0;
#pragma unroll
    for (int u = 0; u < 32; u++) {
        loc[u] = sum;
        sum += g_candcnt[base + u];
    }
    scn[t] = sum;
    __syncthreads();
    for (int off = 1; off < 1024; off <<= 1) {
        int v = (t >= off) ? scn[t - off] : 0;
        __syncthreads();
        scn[t] += v;
        __syncthreads();
    }
    int tb = scn[t] - sum;
#pragma unroll
    for (int u = 0; u < 32; u++) g_candoff[base + u] = tb + loc[u];
}

// ---------------- K3: scatter candidates into CSR ----------------
__global__ __launch_bounds__(256) void k3_scatter() {
    int c = blockIdx.x >> 4;
    int s = (blockIdx.x & 15) * 256 + threadIdx.x;
    if (s >= g_m[c]) return;
    int slot = c * NN + s;
    float v = g_val[slot];
    if (v != 0.0f) {
        int r = g_maxcol[slot];
        int i = __float_as_int(g_saux[slot].y);
        int row = c * NN + r;
        int pos = atomicAdd(&g_cursor[row], 1);
        unsigned long long key =
            ((unsigned long long)__float_as_uint(v) << 32) | (unsigned)i;
        g_cand[g_candoff[row] + pos] = key;
    }
}

// ---------------- K4: per-row top-11 (branchless register network) + averages ----------------
__global__ __launch_bounds__(256) void k4_select(const float* __restrict__ poses,
                                                 const float* __restrict__ boxes) {
    int row = blockIdx.x * 256 + threadIdx.x;
    int c   = row >> 12;
    int cnt = g_candcnt[row];
    int off = g_candoff[row];

    unsigned long long b[KH];
#pragma unroll
    for (int p = 0; p < KH; p++) b[p] = ~0ULL;

    for (int q = 0; q < cnt; q++) {
        unsigned long long x = g_cand[off + q];
#pragma unroll
        for (int p = 0; p < KH; p++) {
            unsigned long long lo = (b[p] < x) ? b[p] : x;
            unsigned long long hi = (b[p] < x) ? x : b[p];
            b[p] = lo;
            x = hi;
        }
    }

    int L  = min(KH, g_m[c]);
    int ns = min(cnt, KH);
    int used = min(ns, L);

    float ps[12];
    float bs4[4];
#pragma unroll
    for (int d = 0; d < 12; d++) ps[d] = 0.0f;
#pragma unroll
    for (int d = 0; d < 4; d++) bs4[d] = 0.0f;

    for (int q = 0; q < used; q++) {
        int a = (int)(b[q] & 0xFFFFFFFFu);
        const float* pp = poses + (size_t)a * (CC * 12) + c * 12;
#pragma unroll
        for (int d = 0; d < 12; d++) ps[d] += pp[d];
        const float* bx = boxes + (size_t)a * (CC * 4) + c * 4;
#pragma unroll
        for (int d = 0; d < 4; d++) bs4[d] += bx[d];
    }
    int sv = (used > 0) ? 1 : 0;
    float den = (float)used;
    g_surv[row] = sv;
#pragma unroll
    for (int d = 0; d < 12; d++) g_pavg[row * 12 + d] = sv ? (ps[d] / den) : 0.0f;
#pragma unroll
    for (int d = 0; d < 4; d++) g_bavg[row * 4 + d] = sv ? (bs4[d] / den) : 0.0f;
}

// ---------------- K5: global selection + output assembly ----------------
__global__ __launch_bounds__(1024) void k5_final(const float* __restrict__ cls,
                                                 float* __restrict__ out, int out_size) {
    __shared__ int scn[1024];
    __shared__ int hist[2048];
    __shared__ int sel[MAXDET];
    __shared__ unsigned arr[MAXDET];
    __shared__ unsigned srt[MAXDET];
    __shared__ int S_sh, b1_sh, t1_sh, b2_sh, t2_sh, e_sh, gcnt, ecnt;
    __shared__ unsigned K100_sh;

    int t = threadIdx.x;
    unsigned keys[32];
    int cnt = 0;
    int base = t * 32;
#pragma unroll
    for (int u = 0; u < 32; u++) {
        int f = base + u;
        unsigned k = 0u;
        if (g_surv[f]) {
            int c = f >> 12, a = f & (NN - 1);
            unsigned ub = __float_as_uint(cls[a * CC + c]);
            k = ub ^ ((ub & 0x80000000u) ? 0xFFFFFFFFu : 0x80000000u);
            cnt++;
        }
        keys[u] = k;
    }
    scn[t] = cnt;
    if (t == 0) { gcnt = 0; ecnt = 0; }
    __syncthreads();
    for (int off = 1; off < 1024; off <<= 1) {
        int v = (t >= off) ? scn[t - off] : 0;
        __syncthreads();
        scn[t] += v;
        __syncthreads();
    }
    int rank = scn[t] - cnt;
    if (cnt > 0 && rank < MAXDET) {
#pragma unroll
        for (int u = 0; u < 32; u++) {
            int f = base + u;
            if (g_surv[f]) {
                if (rank < MAXDET) sel[rank] = f;
                rank++;
            }
        }
    }
    if (t == 1023) S_sh = scn[1023];

    // ---- radix-select level 1 (top 11 bits) ----
    hist[t] = 0; hist[t + 1024] = 0;
    __syncthreads();
#pragma unroll
    for (int u = 0; u < 32; u++) atomicAdd(&hist[keys[u] >> 21], 1);
    __syncthreads();
    if (t == 0) {
        int cum = 0, b;
        for (b = 2047; b >= 0; b--) { cum += hist[b]; if (cum >= MAXDET) break; }
        b1_sh = b;
        t1_sh = MAXDET - (cum - hist[b]);
    }
    __syncthreads();
    unsigned b1 = (unsigned)b1_sh;

    // ---- level 2 (next 11 bits) ----
    hist[t] = 0; hist[t + 1024] = 0;
    __syncthreads();
#pragma unroll
    for (int u = 0; u < 32; u++)
        if ((keys[u] >> 21) == b1) atomicAdd(&hist[(keys[u] >> 10) & 2047u], 1);
    __syncthreads();
    if (t == 0) {
        int tgt = t1_sh, cum = 0, b;
        for (b = 2047; b >= 0; b--) { cum += hist[b]; if (cum >= tgt) break; }
        b2_sh = b;
        t2_sh = tgt - (cum - hist[b]);
    }
    __syncthreads();
    unsigned pre = (b1 << 11) | (unsigned)b2_sh;

    // ---- level 3 (low 10 bits) ----
    hist[t] = 0; hist[t + 1024] = 0;
    __syncthreads();
#pragma unroll
    for (int u = 0; u < 32; u++)
        if ((keys[u] >> 10) == pre) atomicAdd(&hist[keys[u] & 1023u], 1);
    __syncthreads();
    if (t == 0) {
        int tgt = t2_sh, cum = 0, b;
        for (b = 1023; b >= 0; b--) { cum += hist[b]; if (cum >= tgt) break; }
        K100_sh = (pre << 10) | (unsigned)b;
        e_sh = tgt - (cum - hist[b]);
    }
    __syncthreads();
    unsigned K100 = K100_sh;
    int e = e_sh;
    int g = MAXDET - e;

    // ---- collect exactly 100 keys ----
#pragma unroll
    for (int u = 0; u < 32; u++) {
        unsigned k = keys[u];
        if (k > K100) {
            int p = atomicAdd(&gcnt, 1);
            arr[p] = k;
        } else if (k == K100) {
            int p = atomicAdd(&ecnt, 1);
            if (p < e) arr[g + p] = k;
        }
    }
    __syncthreads();

    // ---- rank sort 100 keys descending ----
    if (t < MAXDET) {
        unsigned kt = arr[t];
        int r = 0;
        for (int j = 0; j < MAXDET; j++) {
            unsigned kj = arr[j];
            r += ((kj > kt) || (kj == kt && j < t)) ? 1 : 0;
        }
        srt[r] = kt;
    }
    __syncthreads();

    int S = S_sh;
    // outputs: [scores 100][labels 100][poses 1200][idx 100][boxes 400] = 1900 floats
    for (int q = t; q < MAXDET; q += 1024) {
        float osc = -1.0f;
        if (q < S) {
            unsigned u = srt[q];
            u = (u & 0x80000000u) ? (u ^ 0x80000000u) : ~u;
            osc = __uint_as_float(u);
        }
        if (q < out_size) out[q] = osc;
        float lab = (q < S) ? (float)(sel[q] >> 12) : -1.0f;
        if (100 + q < out_size) out[100 + q] = lab;
        float idx = (q < S) ? (float)(sel[q] & (NN - 1)) : -1.0f;
        if (1400 + q < out_size) out[1400 + q] = idx;
    }
    for (int q = t; q < 1200; q += 1024) {
        int k = q / 12, d = q % 12;
        float v = (k < S) ? g_pavg[sel[k] * 12 + d] : -1.0f;
        if (200 + q < out_size) out[200 + q] = v;
    }
    for (int q = t; q < 400; q += 1024) {
        int k = q >> 2, d = q & 3;
        float v = (k < S) ? g_bavg[sel[k] * 4 + d] : -1.0f;
        if (1500 + q < out_size) out[1500 + q] = v;
    }
}

// ---------------- launcher ----------------
extern "C" void kernel_launch(void* const* d_in, const int* in_sizes, int n_in,
                              void* d_out, int out_size) {
    (void)in_sizes; (void)n_in;
    const float* boxes = (const float*)d_in[1];
    const float* cls   = (const float*)d_in[2];
    const float* poses = (const float*)d_in[3];
    const float* conf  = (const float*)d_in[4];
    float* out = (float*)d_out;

    k0_compact_sort<<<CC, 1024>>>(cls, boxes);
    k1_pairs<<<CC * 32, K1_TILE>>>();
    k1b_values<<<CC * 16, 256>>>(boxes, conf);
    k2_prefix<<<1, 1024>>>();
    k3_scatter<<<CC * 16, 256>>>();
    k4_select<<<NC / 256, 256>>>(poses, boxes);
    k5_final<<<1, 1024>>>(cls, out, out_size);
}

// round 4
// speedup vs baseline: 3.8476x; 2.0639x over previous
#include <cuda_runtime.h>

#define CC 8
#define NN 4096
#define NC (CC*NN)
#define KH 11
#define MAXDET 100
#define XBINS 768          // x1 in [-64, 704), 1px bins
#define XOFF 64

// ---------------- scratch (device globals; no allocation) ----------------
__device__ int    g_m[CC];            // valid count per class
__device__ float4 g_sbox[NC];         // bin-sorted boxes (by slot)
__device__ float2 g_saux[NC];         // sorted aux: (area, orig idx as int bits)
__device__ int    g_rmin[NC];         // per sorted slot: min orig idx of hit (init self)
__device__ int    g_maxcol[NC];       // per slot: winning row r
__device__ float  g_val[NC];          // per slot: candidate value
__device__ int    g_candcnt[NC];      // candidates per row (orig-indexed)
__device__ int    g_candoff[NC];      // within-class CSR offsets
__device__ int    g_cursor[NC];       // scatter cursors
__device__ int    g_ctot[CC];         // per-class candidate totals
__device__ int    g_cbase[CC];        // class base offsets
__device__ unsigned long long g_cand[NC]; // CSR candidates: (valbits<<32)|anchor
__device__ float  g_pavg[NC*12];
__device__ float  g_bavg[NC*4];
__device__ int    g_surv[NC];

// ---------------- shuffle-based inclusive block scan (blockDim.x == 1024) ----------------
__device__ __forceinline__ int blockScanInc(int v, int* ws) {
    const unsigned FULL = 0xFFFFFFFFu;
    int lane = threadIdx.x & 31, w = threadIdx.x >> 5;
#pragma unroll
    for (int o = 1; o < 32; o <<= 1) {
        int n = __shfl_up_sync(FULL, v, o);
        if (lane >= o) v += n;
    }
    if (lane == 31) ws[w] = v;
    __syncthreads();
    if (w == 0) {
        int s = ws[lane];
#pragma unroll
        for (int o = 1; o < 32; o <<= 1) {
            int n = __shfl_up_sync(FULL, s, o);
            if (lane >= o) s += n;
        }
        ws[lane] = s;
    }
    __syncthreads();
    int r = v + ((w > 0) ? ws[w - 1] : 0);
    __syncthreads();
    return r;
}

// ---------------- K0: compact valid anchors + counting sort by x1 bin ----------------
__global__ __launch_bounds__(1024) void k0_sort(const float* __restrict__ cls,
                                                const float* __restrict__ boxes) {
    __shared__ int hist[XBINS];
    __shared__ int sstart[XBINS];
    __shared__ int ws[32];
    __shared__ int m_sh;
    int c = blockIdx.x;
    int t = threadIdx.x;

    for (int b = t; b < XBINS; b += 1024) hist[b] = 0;
    // zero per-row counters for this class
    int4 z4 = make_int4(0, 0, 0, 0);
    *(int4*)&g_candcnt[c * NN + t * 4] = z4;
    *(int4*)&g_cursor[c * NN + t * 4] = z4;
    __syncthreads();

    bool   myv[4];
    int    mybin[4];
    float4 mybox[4];
#pragma unroll
    for (int u = 0; u < 4; u++) {
        int a = t + u * 1024;
        float sc = cls[a * CC + c];
        myv[u] = sc > 0.5f;
        if (myv[u]) {
            mybox[u] = *(const float4*)(boxes + (size_t)a * (CC * 4) + c * 4);
            int b = __float2int_rd(mybox[u].x) + XOFF;
            b = max(0, min(XBINS - 1, b));
            mybin[u] = b;
            atomicAdd(&hist[b], 1);
        }
    }
    __syncthreads();

    // exclusive scan over bins
    int hv = (t < XBINS) ? hist[t] : 0;
    int inc = blockScanInc(hv, ws);
    if (t < XBINS) sstart[t] = inc - hv;
    if (t == XBINS - 1) { m_sh = inc; g_m[c] = inc; }
    __syncthreads();
    // reuse hist as per-bin cursors
    for (int b = t; b < XBINS; b += 1024) hist[b] = 0;
    __syncthreads();

#pragma unroll
    for (int u = 0; u < 4; u++) {
        if (myv[u]) {
            int a = t + u * 1024;
            int pos = sstart[mybin[u]] + atomicAdd(&hist[mybin[u]], 1);
            int slot = c * NN + pos;
            float4 b = mybox[u];
            g_sbox[slot] = b;
            g_saux[slot] = make_float2((b.z - b.x + 1.0f) * (b.w - b.y + 1.0f),
                                       __int_as_float(a));
            g_rmin[slot] = a;   // self hit baseline
        }
    }
}

// ---------------- K1: symmetric forward pair scan (bin-sorted by x1) ----------------
#define K1_TILE 128
#define K1_SPAN 1024
__global__ __launch_bounds__(K1_TILE) void k1_pairs() {
    __shared__ float4 tb[K1_SPAN];
    __shared__ float2 ta[K1_SPAN];

    int c  = blockIdx.x >> 5;
    int S0 = (blockIdx.x & 31) * K1_TILE;
    int m  = g_m[c];
    if (S0 >= m) return;

    for (int k = threadIdx.x; k < K1_SPAN; k += K1_TILE) {
        int s = S0 + k;
        if (s < m) {
            tb[k] = g_sbox[c * NN + s];
            ta[k] = g_saux[c * NN + s];
        } else {
            tb[k] = make_float4(3.0e38f, 0.0f, -10.0f, -10.0f); // x1=+inf sentinel
            ta[k] = make_float2(1.0f, __int_as_float(0));
        }
    }
    __syncthreads();

    int s = S0 + threadIdx.x;
    if (s >= m) return;

    float4 a    = tb[threadIdx.x];
    float areaA = ta[threadIdx.x].x;
    int   origI = __float_as_int(ta[threadIdx.x].y);
    float limit = a.z + 2.0f;   // (x2_s + 1) + 1px bin-order slop

    int ts = threadIdx.x + 1;
    while (true) {
        float4 b; float2 ax;
        if (ts < K1_SPAN) {
            b  = tb[ts];
            ax = ta[ts];
        } else {
            int gs = S0 + ts;
            if (gs >= m) break;
            b  = g_sbox[c * NN + gs];
            ax = g_saux[c * NN + gs];
        }
        if (b.x >= limit) break;

        float x1 = fmaxf(a.x, b.x);
        float y1 = fmaxf(a.y, b.y);
        float x2 = fminf(a.z, b.z);
        float y2 = fminf(a.w, b.w);
        float w = x2 - x1 + 1.0f;
        float h = y2 - y1 + 1.0f;
        float inter = w * h;
        float den = areaA + ax.x - inter;
        if (w > 0.0f && h > 0.0f && inter > 0.5f * den) {
            int origJ = __float_as_int(ax.y);
            atomicMin(&g_rmin[c * NN + s], origJ);
            atomicMin(&g_rmin[c * NN + S0 + ts], origI);
        }
        ts++;
    }
}

// ---------------- K1b: per-anchor winner -> exact value + row counts ----------------
__global__ __launch_bounds__(256) void k1b_values(const float* __restrict__ boxes,
                                                  const float* __restrict__ conf) {
    int c = blockIdx.x >> 4;
    int s = (blockIdx.x & 15) * 256 + threadIdx.x;
    int m = g_m[c];
    if (s >= m) return;

    int slot = c * NN + s;
    int r    = g_rmin[slot];
    int i    = __float_as_int(g_saux[slot].y);

    float v = 0.0f;
    if (r != i) {
        float4 bi = g_sbox[slot];
        float4 br = *(const float4*)(boxes + (size_t)r * (CC * 4) + c * 4);
        float x1 = fmaxf(bi.x, br.x);
        float y1 = fmaxf(bi.y, br.y);
        float x2 = fminf(bi.z, br.z);
        float y2 = fminf(bi.w, br.w);
        float w = x2 - x1 + 1.0f;
        float h = y2 - y1 + 1.0f;
        float inter = w * h;
        float areaI = (bi.z - bi.x + 1.0f) * (bi.w - bi.y + 1.0f);
        float areaR = (br.z - br.x + 1.0f) * (br.w - br.y + 1.0f);
        float den = areaI + areaR - inter;
        float ov = (den == 0.0f) ? 0.0f : inter / den;
        if (w <= 0.0f || h <= 0.0f) ov = 0.0f;
        v = (1.0f - ov) * conf[i * CC + c];
    }
    g_maxcol[slot] = r;
    g_val[slot]    = v;
    if (r != i && v != 0.0f) atomicAdd(&g_candcnt[c * NN + r], 1);
}

// ---------------- K2a: per-class exclusive scan over 4096 counts ----------------
__global__ __launch_bounds__(1024) void k2a_scan() {
    __shared__ int ws[32];
    int c = blockIdx.x;
    int t = threadIdx.x;
    int4 v4 = *(const int4*)&g_candcnt[c * NN + t * 4];
    int s0 = v4.x;
    int s1 = s0 + v4.y;
    int s2 = s1 + v4.z;
    int s3 = s2 + v4.w;
    int inc = blockScanInc(s3, ws);
    int base = inc - s3;
    int4 off = make_int4(base, base + s0, base + s1, base + s2);
    *(int4*)&g_candoff[c * NN + t * 4] = off;
    if (t == 1023) g_ctot[c] = inc;
}

// ---------------- K2b: class base scan ----------------
__global__ void k2b_base() {
    if (threadIdx.x == 0) {
        int s = 0;
        for (int c = 0; c < CC; c++) { g_cbase[c] = s; s += g_ctot[c]; }
    }
}

// ---------------- K3: scatter candidates into CSR ----------------
__global__ __launch_bounds__(256) void k3_scatter() {
    int c = blockIdx.x >> 4;
    int s = (blockIdx.x & 15) * 256 + threadIdx.x;
    if (s >= g_m[c]) return;
    int slot = c * NN + s;
    float v = g_val[slot];
    if (v != 0.0f) {
        int r = g_maxcol[slot];
        int i = __float_as_int(g_saux[slot].y);
        int row = c * NN + r;
        int pos = atomicAdd(&g_cursor[row], 1);
        unsigned long long key =
            ((unsigned long long)__float_as_uint(v) << 32) | (unsigned)i;
        g_cand[g_cbase[c] + g_candoff[row] + pos] = key;
    }
}

// ---------------- K4: per-row top-11 + averages (writes only survivors) ----------------
__global__ __launch_bounds__(256) void k4_select(const float* __restrict__ poses,
                                                 const float* __restrict__ boxes) {
    int row = blockIdx.x * 256 + threadIdx.x;
    int c   = row >> 12;
    int cnt = g_candcnt[row];

    int used = 0;
    if (cnt > 0) {
        int off = g_cbase[c] + g_candoff[row];
        unsigned long long b[KH];
#pragma unroll
        for (int p = 0; p < KH; p++) b[p] = ~0ULL;
        for (int q = 0; q < cnt; q++) {
            unsigned long long x = g_cand[off + q];
#pragma unroll
            for (int p = 0; p < KH; p++) {
                unsigned long long lo = (b[p] < x) ? b[p] : x;
                unsigned long long hi = (b[p] < x) ? x : b[p];
                b[p] = lo;
                x = hi;
            }
        }
        int L  = min(KH, g_m[c]);
        int ns = min(cnt, KH);
        used = min(ns, L);

        if (used > 0) {
            float ps[12];
            float bs4[4];
#pragma unroll
            for (int d = 0; d < 12; d++) ps[d] = 0.0f;
#pragma unroll
            for (int d = 0; d < 4; d++) bs4[d] = 0.0f;
            for (int q = 0; q < used; q++) {
                int a = (int)(b[q] & 0xFFFFFFFFu);
                const float* pp = poses + (size_t)a * (CC * 12) + c * 12;
#pragma unroll
                for (int d = 0; d < 12; d++) ps[d] += pp[d];
                const float* bx = boxes + (size_t)a * (CC * 4) + c * 4;
#pragma unroll
                for (int d = 0; d < 4; d++) bs4[d] += bx[d];
            }
            float den = (float)used;
#pragma unroll
            for (int d = 0; d < 12; d++) g_pavg[row * 12 + d] = ps[d] / den;
#pragma unroll
            for (int d = 0; d < 4; d++) g_bavg[row * 4 + d] = bs4[d] / den;
        }
    }
    g_surv[row] = (used > 0) ? 1 : 0;
}

// ---------------- K5: global selection + output assembly ----------------
__device__ __forceinline__ void find_thr(const int* hist, int nbins, int target,
                                         volatile int* out_b, volatile int* out_t,
                                         int* ws) {
    int t = threadIdx.x;
    if (t == 0) { *out_b = 0; *out_t = 0; }
    __syncthreads();
    if (nbins == 2048) {
        int b1 = 2047 - 2 * t;
        int b0 = b1 - 1;
        int h1 = hist[b1], h0 = hist[b0];
        int inc = blockScanInc(h1 + h0, ws);     // suffix sum at b0
        int suf0 = inc;
        int suf1 = inc - h0;
        if (suf1 >= target && suf1 - h1 < target) { *out_b = b1; *out_t = target - (suf1 - h1); }
        if (suf0 >= target && suf0 - h0 < target) { *out_b = b0; *out_t = target - (suf0 - h0); }
    } else {
        int b = 1023 - t;
        int h = hist[b];
        int inc = blockScanInc(h, ws);
        if (inc >= target && inc - h < target) { *out_b = b; *out_t = target - (inc - h); }
    }
    __syncthreads();
}

__global__ __launch_bounds__(1024) void k5_final(const float* __restrict__ cls,
                                                 float* __restrict__ out, int out_size) {
    __shared__ int hist[2048];
    __shared__ int ws[32];
    __shared__ int sel[MAXDET];
    __shared__ unsigned arr[MAXDET];
    __shared__ unsigned srt[MAXDET];
    __shared__ volatile int b_sh, t_sh;
    __shared__ int S_sh, t1_sh, b1_sh, e_sh, gcnt, ecnt;
    __shared__ unsigned pre_sh, K100_sh;

    int t = threadIdx.x;
    int base = t * 32;

    // load survivors (int4) and build keys
    int sv[32];
#pragma unroll
    for (int u = 0; u < 32; u += 4) {
        int4 s4 = *(const int4*)&g_surv[base + u];
        sv[u] = s4.x; sv[u + 1] = s4.y; sv[u + 2] = s4.z; sv[u + 3] = s4.w;
    }
    unsigned keys[32];
    int cnt = 0;
#pragma unroll
    for (int u = 0; u < 32; u++) {
        unsigned k = 0u;
        if (sv[u]) {
            int f = base + u;
            int c = f >> 12, a = f & (NN - 1);
            unsigned ub = __float_as_uint(cls[a * CC + c]);
            k = ub ^ ((ub & 0x80000000u) ? 0xFFFFFFFFu : 0x80000000u);
            cnt++;
        }
        keys[u] = k;
    }
    if (t == 0) { gcnt = 0; ecnt = 0; }
    int incS = blockScanInc(cnt, ws);
    int rank = incS - cnt;
    if (cnt > 0 && rank < MAXDET) {
#pragma unroll
        for (int u = 0; u < 32; u++) {
            if (sv[u]) {
                if (rank < MAXDET) sel[rank] = base + u;
                rank++;
            }
        }
    }
    if (t == 1023) S_sh = incS;

    // ---- radix-select level 1 (top 11 bits) ----
    hist[t] = 0; hist[t + 1024] = 0;
    __syncthreads();
#pragma unroll
    for (int u = 0; u < 32; u++) atomicAdd(&hist[keys[u] >> 21], 1);
    __syncthreads();
    find_thr(hist, 2048, MAXDET, &b_sh, &t_sh, ws);
    if (t == 0) { b1_sh = b_sh; t1_sh = t_sh; }
    __syncthreads();
    unsigned b1 = (unsigned)b1_sh;
    int tgt2 = t1_sh;

    // ---- level 2 (next 11 bits) ----
    hist[t] = 0; hist[t + 1024] = 0;
    __syncthreads();
#pragma unroll
    for (int u = 0; u < 32; u++)
        if ((keys[u] >> 21) == b1) atomicAdd(&hist[(keys[u] >> 10) & 2047u], 1);
    __syncthreads();
    find_thr(hist, 2048, tgt2, &b_sh, &t_sh, ws);
    if (t == 0) { pre_sh = (b1 << 11) | (unsigned)b_sh; e_sh = t_sh; }
    __syncthreads();
    unsigned pre = pre_sh;
    int tgt3 = e_sh;

    // ---- level 3 (low 10 bits) ----
    hist[t] = 0; hist[t + 1024] = 0;
    __syncthreads();
#pragma unroll
    for (int u = 0; u < 32; u++)
        if ((keys[u] >> 10) == pre) atomicAdd(&hist[keys[u] & 1023u], 1);
    __syncthreads();
    find_thr(hist, 1024, tgt3, &b_sh, &t_sh, ws);
    if (t == 0) { K100_sh = (pre << 10) | (unsigned)b_sh; e_sh = t_sh; }
    __syncthreads();
    unsigned K100 = K100_sh;
    int e = e_sh;
    int g = MAXDET - e;

    // ---- collect exactly 100 keys ----
#pragma unroll
    for (int u = 0; u < 32; u++) {
        unsigned k = keys[u];
        if (k > K100) {
            int p = atomicAdd(&gcnt, 1);
            if (p < g) arr[p] = k;
        } else if (k == K100) {
            int p = atomicAdd(&ecnt, 1);
            if (p < e) arr[g + p] = k;
        }
    }
    __syncthreads();

    // ---- rank sort 100 keys descending ----
    if (t < MAXDET) {
        unsigned kt = arr[t];
        int r = 0;
        for (int j = 0; j < MAXDET; j++) {
            unsigned kj = arr[j];
            r += ((kj > kt) || (kj == kt && j < t)) ? 1 : 0;
        }
        srt[r] = kt;
    }
    __syncthreads();

    int S = S_sh;
    // outputs: [scores 100][labels 100][poses 1200][idx 100][boxes 400] = 1900 floats
    for (int q = t; q < MAXDET; q += 1024) {
        float osc = -1.0f;
        if (q < S) {
            unsigned u = srt[q];
            u = (u & 0x80000000u) ? (u ^ 0x80000000u) : ~u;
            osc = __uint_as_float(u);
        }
        if (q < out_size) out[q] = osc;
        float lab = (q < S) ? (float)(sel[q] >> 12) : -1.0f;
        if (100 + q < out_size) out[100 + q] = lab;
        float idx = (q < S) ? (float)(sel[q] & (NN - 1)) : -1.0f;
        if (1400 + q < out_size) out[1400 + q] = idx;
    }
    for (int q = t; q < 1200; q += 1024) {
        int k = q / 12, d = q % 12;
        float v = (k < S) ? g_pavg[sel[k] * 12 + d] : -1.0f;
        if (200 + q < out_size) out[200 + q] = v;
    }
    for (int q = t; q < 400; q += 1024) {
        int k = q >> 2, d = q & 3;
        float v = (k < S) ? g_bavg[sel[k] * 4 + d] : -1.0f;
        if (1500 + q < out_size) out[1500 + q] = v;
    }
}

// ---------------- launcher ----------------
extern "C" void kernel_launch(void* const* d_in, const int* in_sizes, int n_in,
                              void* d_out, int out_size) {
    (void)in_sizes; (void)n_in;
    const float* boxes = (const float*)d_in[1];
    const float* cls   = (const float*)d_in[2];
    const float* poses = (const float*)d_in[3];
    const float* conf  = (const float*)d_in[4];
    float* out = (float*)d_out;

    k0_sort<<<CC, 1024>>>(cls, boxes);
    k1_pairs<<<CC * 32, K1_TILE>>>();
    k1b_values<<<CC * 16, 256>>>(boxes, conf);
    k2a_scan<<<CC, 1024>>>();
    k2b_base<<<1, 32>>>();
    k3_scatter<<<CC * 16, 256>>>();
    k4_select<<<NC / 256, 256>>>(poses, boxes);
    k5_final<<<1, 1024>>>(cls, out, out_size);
}

// round 5
// speedup vs baseline: 5.3154x; 1.3815x over previous
#include <cuda_runtime.h>

#define CC 8
#define NN 4096
#define NC (CC*NN)
#define KH 11
#define MAXDET 100
#define XBINS 768          // x1 in [-64, 704), 1px bins
#define XOFF 64

// ---------------- scratch (device globals; no allocation) ----------------
__device__ int    g_m[CC];            // valid count per class
__device__ float4 g_sbox[NC];         // bin-sorted boxes (by slot)
__device__ float2 g_saux[NC];         // sorted aux: (area, orig idx as int bits)
__device__ int    g_rmin[NC];         // per sorted slot: min orig idx of hit (init self)
__device__ float  g_pavg[NC*12];
__device__ float  g_bavg[NC*4];
__device__ int    g_surv[NC];

// ---------------- shuffle-based inclusive block scan (blockDim.x == 1024) ----------------
__device__ __forceinline__ int blockScanInc(int v, int* ws) {
    const unsigned FULL = 0xFFFFFFFFu;
    int lane = threadIdx.x & 31, w = threadIdx.x >> 5;
#pragma unroll
    for (int o = 1; o < 32; o <<= 1) {
        int n = __shfl_up_sync(FULL, v, o);
        if (lane >= o) v += n;
    }
    if (lane == 31) ws[w] = v;
    __syncthreads();
    if (w == 0) {
        int s = ws[lane];
#pragma unroll
        for (int o = 1; o < 32; o <<= 1) {
            int n = __shfl_up_sync(FULL, s, o);
            if (lane >= o) s += n;
        }
        ws[lane] = s;
    }
    __syncthreads();
    int r = v + ((w > 0) ? ws[w - 1] : 0);
    __syncthreads();
    return r;
}

// ---------------- K0: compact valid anchors + counting sort by x1 bin ----------------
__global__ __launch_bounds__(1024) void k0_sort(const float* __restrict__ cls,
                                                const float* __restrict__ boxes) {
    __shared__ int hist[XBINS];
    __shared__ int sstart[XBINS];
    __shared__ int ws[32];
    int c = blockIdx.x;
    int t = threadIdx.x;

    for (int b = t; b < XBINS; b += 1024) hist[b] = 0;
    __syncthreads();

    bool   myv[4];
    int    mybin[4];
    float4 mybox[4];
#pragma unroll
    for (int u = 0; u < 4; u++) {
        int a = t + u * 1024;
        float sc = cls[a * CC + c];
        myv[u] = sc > 0.5f;
        if (myv[u]) {
            mybox[u] = *(const float4*)(boxes + (size_t)a * (CC * 4) + c * 4);
            int b = __float2int_rd(mybox[u].x) + XOFF;
            b = max(0, min(XBINS - 1, b));
            mybin[u] = b;
            atomicAdd(&hist[b], 1);
        }
    }
    __syncthreads();

    // exclusive scan over bins
    int hv = (t < XBINS) ? hist[t] : 0;
    int inc = blockScanInc(hv, ws);
    if (t < XBINS) sstart[t] = inc - hv;
    if (t == XBINS - 1) g_m[c] = inc;
    __syncthreads();
    // reuse hist as per-bin cursors
    for (int b = t; b < XBINS; b += 1024) hist[b] = 0;
    __syncthreads();

#pragma unroll
    for (int u = 0; u < 4; u++) {
        if (myv[u]) {
            int a = t + u * 1024;
            int pos = sstart[mybin[u]] + atomicAdd(&hist[mybin[u]], 1);
            int slot = c * NN + pos;
            float4 b = mybox[u];
            g_sbox[slot] = b;
            g_saux[slot] = make_float2((b.z - b.x + 1.0f) * (b.w - b.y + 1.0f),
                                       __int_as_float(a));
            g_rmin[slot] = a;   // self hit baseline
        }
    }
}

// ---------------- K1: symmetric forward pair scan, 8 sub-threads per anchor ----------------
#define K1_TILE 64
#define K1_SUB 8
#define K1_THREADS 512
#define K1_SPAN 1024
__global__ __launch_bounds__(K1_THREADS) void k1_pairs() {
    __shared__ float4 tb[K1_SPAN];
    __shared__ float2 ta[K1_SPAN];

    int c  = blockIdx.x >> 6;           // 64 tiles per class
    int S0 = (blockIdx.x & 63) * K1_TILE;
    int m  = g_m[c];
    if (S0 >= m) return;

    for (int k = threadIdx.x; k < K1_SPAN; k += K1_THREADS) {
        int s = S0 + k;
        if (s < m) {
            tb[k] = g_sbox[c * NN + s];
            ta[k] = g_saux[c * NN + s];
        } else {
            tb[k] = make_float4(3.0e38f, 0.0f, -10.0f, -10.0f); // x1=+inf sentinel
            ta[k] = make_float2(1.0f, __int_as_float(0));
        }
    }
    __syncthreads();

    int ai  = threadIdx.x & (K1_TILE - 1);     // anchor within tile
    int sub = threadIdx.x >> 6;                // 0..7
    int s = S0 + ai;
    if (s >= m) return;

    float4 a    = tb[ai];
    float areaA = ta[ai].x;
    int   origI = __float_as_int(ta[ai].y);
    float limit = a.z + 2.0f;   // (x2_s + 1) + 1px bin-order slop

    for (int ts = ai + 1 + sub; ; ts += K1_SUB) {
        float4 b; float2 ax;
        if (ts < K1_SPAN) {
            b  = tb[ts];
            ax = ta[ts];
        } else {
            int gs = S0 + ts;
            if (gs >= m) break;
            b  = g_sbox[c * NN + gs];
            ax = g_saux[c * NN + gs];
        }
        if (b.x >= limit) break;

        float x1 = fmaxf(a.x, b.x);
        float y1 = fmaxf(a.y, b.y);
        float x2 = fminf(a.z, b.z);
        float y2 = fminf(a.w, b.w);
        float w = x2 - x1 + 1.0f;
        float h = y2 - y1 + 1.0f;
        float inter = w * h;
        float den = areaA + ax.x - inter;
        if (w > 0.0f && h > 0.0f && inter > 0.5f * den) {
            int origJ = __float_as_int(ax.y);
            atomicMin(&g_rmin[c * NN + s], origJ);
            atomicMin(&g_rmin[c * NN + S0 + ts], origI);
        }
    }
}

// ---------------- K2: fused values + scan + scatter + top-11 select (one block/class) ----------------
// dynamic smem layout: scnt[4096] | soff[4096] | cand[4096] (u64)
__global__ __launch_bounds__(1024) void k2_fused(const float* __restrict__ boxes,
                                                 const float* __restrict__ conf,
                                                 const float* __restrict__ poses) {
    extern __shared__ int sm[];
    int* scnt = sm;                    // counts, later cursors
    int* soff = sm + NN;               // exclusive offsets
    unsigned long long* cand = (unsigned long long*)(sm + 2 * NN);
    __shared__ int ws[32];

    int c = blockIdx.x;
    int t = threadIdx.x;
    int m = g_m[c];

    *(int4*)&scnt[t * 4] = make_int4(0, 0, 0, 0);
    __syncthreads();

    // --- phase 1: per-slot winner value; count per target row (smem atomics) ---
    float vv[4];
    int   vi[4], vr[4];
    bool  has[4];
#pragma unroll
    for (int u = 0; u < 4; u++) {
        has[u] = false;
        int s = t + u * 1024;
        if (s < m) {
            int slot = c * NN + s;
            int r = g_rmin[slot];
            int i = __float_as_int(g_saux[slot].y);
            if (r != i) {
                float4 bi = g_sbox[slot];
                float4 br = *(const float4*)(boxes + (size_t)r * (CC * 4) + c * 4);
                float x1 = fmaxf(bi.x, br.x);
                float y1 = fmaxf(bi.y, br.y);
                float x2 = fminf(bi.z, br.z);
                float y2 = fminf(bi.w, br.w);
                float w = x2 - x1 + 1.0f;
                float h = y2 - y1 + 1.0f;
                float inter = w * h;
                float areaI = (bi.z - bi.x + 1.0f) * (bi.w - bi.y + 1.0f);
                float areaR = (br.z - br.x + 1.0f) * (br.w - br.y + 1.0f);
                float den = areaI + areaR - inter;
                float ov = (den == 0.0f) ? 0.0f : inter / den;
                if (w <= 0.0f || h <= 0.0f) ov = 0.0f;
                float v = (1.0f - ov) * conf[i * CC + c];
                if (v != 0.0f) {
                    vv[u] = v; vi[u] = i; vr[u] = r; has[u] = true;
                    atomicAdd(&scnt[r], 1);
                }
            }
        }
    }
    __syncthreads();

    // --- phase 2: exclusive scan over 4096 row counts (thread t owns rows 4t..4t+3) ---
    int rcnt[4];
    int run = 0;
    int pre[4];
#pragma unroll
    for (int u = 0; u < 4; u++) {
        rcnt[u] = scnt[t * 4 + u];
        pre[u] = run;
        run += rcnt[u];
    }
    int incv = blockScanInc(run, ws);
    int base = incv - run;
#pragma unroll
    for (int u = 0; u < 4; u++) soff[t * 4 + u] = base + pre[u];
    __syncthreads();
    // zero cursors (reuse scnt)
    *(int4*)&scnt[t * 4] = make_int4(0, 0, 0, 0);
    __syncthreads();

    // --- phase 3: scatter candidates into smem CSR ---
#pragma unroll
    for (int u = 0; u < 4; u++) {
        if (has[u]) {
            int r = vr[u];
            int pos = soff[r] + atomicAdd(&scnt[r], 1);
            cand[pos] = ((unsigned long long)__float_as_uint(vv[u]) << 32) | (unsigned)vi[u];
        }
    }
    __syncthreads();

    // --- phase 4: per-row top-11 + averages ---
    int L = min(KH, m);
#pragma unroll
    for (int u = 0; u < 4; u++) {
        int row = t * 4 + u;
        int cnt = rcnt[u];
        int used = 0;
        if (cnt > 0) {
            int off = soff[row];
            unsigned long long b[KH];
#pragma unroll
            for (int p = 0; p < KH; p++) b[p] = ~0ULL;
            for (int q = 0; q < cnt; q++) {
                unsigned long long x = cand[off + q];
#pragma unroll
                for (int p = 0; p < KH; p++) {
                    unsigned long long lo = (b[p] < x) ? b[p] : x;
                    unsigned long long hi = (b[p] < x) ? x : b[p];
                    b[p] = lo;
                    x = hi;
                }
            }
            used = min(min(cnt, KH), L);
            if (used > 0) {
                float ps[12], bs4[4];
#pragma unroll
                for (int d = 0; d < 12; d++) ps[d] = 0.0f;
#pragma unroll
                for (int d = 0; d < 4; d++) bs4[d] = 0.0f;
                for (int q = 0; q < used; q++) {
                    int a = (int)(b[q] & 0xFFFFFFFFu);
                    const float* pp = poses + (size_t)a * (CC * 12) + c * 12;
#pragma unroll
                    for (int d = 0; d < 12; d++) ps[d] += pp[d];
                    const float* bx = boxes + (size_t)a * (CC * 4) + c * 4;
#pragma unroll
                    for (int d = 0; d < 4; d++) bs4[d] += bx[d];
                }
                float den = (float)used;
                int grow = c * NN + row;
#pragma unroll
                for (int d = 0; d < 12; d++) g_pavg[grow * 12 + d] = ps[d] / den;
#pragma unroll
                for (int d = 0; d < 4; d++) g_bavg[grow * 4 + d] = bs4[d] / den;
            }
        }
        g_surv[c * NN + row] = (used > 0) ? 1 : 0;
    }
}

// ---------------- K5: global selection + output assembly ----------------
__device__ __forceinline__ void find_thr(const int* hist, int nbins, int target,
                                         volatile int* out_b, volatile int* out_t,
                                         int* ws) {
    int t = threadIdx.x;
    if (t == 0) { *out_b = 0; *out_t = 0; }
    __syncthreads();
    if (nbins == 2048) {
        int b1 = 2047 - 2 * t;
        int b0 = b1 - 1;
        int h1 = hist[b1], h0 = hist[b0];
        int inc = blockScanInc(h1 + h0, ws);     // suffix sum at b0
        int suf0 = inc;
        int suf1 = inc - h0;
        if (suf1 >= target && suf1 - h1 < target) { *out_b = b1; *out_t = target - (suf1 - h1); }
        if (suf0 >= target && suf0 - h0 < target) { *out_b = b0; *out_t = target - (suf0 - h0); }
    } else {
        int b = 1023 - t;
        int h = hist[b];
        int inc = blockScanInc(h, ws);
        if (inc >= target && inc - h < target) { *out_b = b; *out_t = target - (inc - h); }
    }
    __syncthreads();
}

__global__ __launch_bounds__(1024) void k5_final(const float* __restrict__ cls,
                                                 float* __restrict__ out, int out_size) {
    __shared__ int hist[2048];
    __shared__ int ws[32];
    __shared__ int sel[MAXDET];
    __shared__ unsigned arr[MAXDET];
    __shared__ unsigned srt[MAXDET];
    __shared__ volatile int b_sh, t_sh;
    __shared__ int S_sh, t1_sh, b1_sh, e_sh, gcnt, ecnt;
    __shared__ unsigned pre_sh, K100_sh;

    int t = threadIdx.x;
    int base = t * 32;

    // load survivors (int4) and build keys
    int sv[32];
#pragma unroll
    for (int u = 0; u < 32; u += 4) {
        int4 s4 = *(const int4*)&g_surv[base + u];
        sv[u] = s4.x; sv[u + 1] = s4.y; sv[u + 2] = s4.z; sv[u + 3] = s4.w;
    }
    unsigned keys[32];
    int cnt = 0;
#pragma unroll
    for (int u = 0; u < 32; u++) {
        unsigned k = 0u;
        if (sv[u]) {
            int f = base + u;
            int c = f >> 12, a = f & (NN - 1);
            unsigned ub = __float_as_uint(cls[a * CC + c]);
            k = ub ^ ((ub & 0x80000000u) ? 0xFFFFFFFFu : 0x80000000u);
            cnt++;
        }
        keys[u] = k;
    }
    if (t == 0) { gcnt = 0; ecnt = 0; }
    int incS = blockScanInc(cnt, ws);
    int rank = incS - cnt;
    if (cnt > 0 && rank < MAXDET) {
#pragma unroll
        for (int u = 0; u < 32; u++) {
            if (sv[u]) {
                if (rank < MAXDET) sel[rank] = base + u;
                rank++;
            }
        }
    }
    if (t == 1023) S_sh = incS;

    // ---- radix-select level 1 (top 11 bits) ----
    hist[t] = 0; hist[t + 1024] = 0;
    __syncthreads();
#pragma unroll
    for (int u = 0; u < 32; u++) atomicAdd(&hist[keys[u] >> 21], 1);
    __syncthreads();
    find_thr(hist, 2048, MAXDET, &b_sh, &t_sh, ws);
    if (t == 0) { b1_sh = b_sh; t1_sh = t_sh; }
    __syncthreads();
    unsigned b1 = (unsigned)b1_sh;
    int tgt2 = t1_sh;

    // ---- level 2 (next 11 bits) ----
    hist[t] = 0; hist[t + 1024] = 0;
    __syncthreads();
#pragma unroll
    for (int u = 0; u < 32; u++)
        if ((keys[u] >> 21) == b1) atomicAdd(&hist[(keys[u] >> 10) & 2047u], 1);
    __syncthreads();
    find_thr(hist, 2048, tgt2, &b_sh, &t_sh, ws);
    if (t == 0) { pre_sh = (b1 << 11) | (unsigned)b_sh; e_sh = t_sh; }
    __syncthreads();
    unsigned pre = pre_sh;
    int tgt3 = e_sh;

    // ---- level 3 (low 10 bits) ----
    hist[t] = 0; hist[t + 1024] = 0;
    __syncthreads();
#pragma unroll
    for (int u = 0; u < 32; u++)
        if ((keys[u] >> 10) == pre) atomicAdd(&hist[keys[u] & 1023u], 1);
    __syncthreads();
    find_thr(hist, 1024, tgt3, &b_sh, &t_sh, ws);
    if (t == 0) { K100_sh = (pre << 10) | (unsigned)b_sh; e_sh = t_sh; }
    __syncthreads();
    unsigned K100 = K100_sh;
    int e = e_sh;
    int g = MAXDET - e;

    // ---- collect exactly 100 keys ----
#pragma unroll
    for (int u = 0; u < 32; u++) {
        unsigned k = keys[u];
        if (k > K100) {
            int p = atomicAdd(&gcnt, 1);
            if (p < g) arr[p] = k;
        } else if (k == K100) {
            int p = atomicAdd(&ecnt, 1);
            if (p < e) arr[g + p] = k;
        }
    }
    __syncthreads();

    // ---- rank sort 100 keys descending ----
    if (t < MAXDET) {
        unsigned kt = arr[t];
        int r = 0;
        for (int j = 0; j < MAXDET; j++) {
            unsigned kj = arr[j];
            r += ((kj > kt) || (kj == kt && j < t)) ? 1 : 0;
        }
        srt[r] = kt;
    }
    __syncthreads();

    int S = S_sh;
    // outputs: [scores 100][labels 100][poses 1200][idx 100][boxes 400] = 1900 floats
    for (int q = t; q < MAXDET; q += 1024) {
        float osc = -1.0f;
        if (q < S) {
            unsigned u = srt[q];
            u = (u & 0x80000000u) ? (u ^ 0x80000000u) : ~u;
            osc = __uint_as_float(u);
        }
        if (q < out_size) out[q] = osc;
        float lab = (q < S) ? (float)(sel[q] >> 12) : -1.0f;
        if (100 + q < out_size) out[100 + q] = lab;
        float idx = (q < S) ? (float)(sel[q] & (NN - 1)) : -1.0f;
        if (1400 + q < out_size) out[1400 + q] = idx;
    }
    for (int q = t; q < 1200; q += 1024) {
        int k = q / 12, d = q % 12;
        float v = (k < S) ? g_pavg[sel[k] * 12 + d] : -1.0f;
        if (200 + q < out_size) out[200 + q] = v;
    }
    for (int q = t; q < 400; q += 1024) {
        int k = q >> 2, d = q & 3;
        float v = (k < S) ? g_bavg[sel[k] * 4 + d] : -1.0f;
        if (1500 + q < out_size) out[1500 + q] = v;
    }
}

// ---------------- launcher ----------------
extern "C" void kernel_launch(void* const* d_in, const int* in_sizes, int n_in,
                              void* d_out, int out_size) {
    (void)in_sizes; (void)n_in;
    const float* boxes = (const float*)d_in[1];
    const float* cls   = (const float*)d_in[2];
    const float* poses = (const float*)d_in[3];
    const float* conf  = (const float*)d_in[4];
    float* out = (float*)d_out;

    int smem2 = 2 * NN * (int)sizeof(int) + NN * (int)sizeof(unsigned long long) + 128;
    cudaFuncSetAttribute(k2_fused, cudaFuncAttributeMaxDynamicSharedMemorySize, smem2);

    k0_sort<<<CC, 1024>>>(cls, boxes);
    k1_pairs<<<CC * 64, K1_THREADS>>>();
    k2_fused<<<CC, 1024, smem2>>>(boxes, conf, poses);
    k5_final<<<1, 1024>>>(cls, out, out_size);
}

// round 6
// speedup vs baseline: 6.1993x; 1.1663x over previous
#include <cuda_runtime.h>

#define CC 8
#define NN 4096
#define NC (CC*NN)
#define KH 11
#define MAXDET 100
#define XBINS 768          // x1 in [-64, 704), 1px bins
#define XOFF 64

// ---------------- scratch (device globals; no allocation) ----------------
__device__ int    g_m[CC];            // valid count per class
__device__ float4 g_sbox[NC];         // bin-sorted boxes (by slot)
__device__ float2 g_saux[NC];         // sorted aux: (area, orig idx as int bits)
__device__ int    g_rmin[NC];         // per sorted slot: min orig idx of hit (init self)
__device__ float  g_pavg[NC*12];
__device__ float  g_bavg[NC*4];
__device__ int    g_scount[CC];       // survivors per class
__device__ int    g_srow[NC];         // compacted survivor rows (ascending per class)
__device__ unsigned g_skey[NC];       // compacted survivor keys (monotone score bits)

// ---------------- shuffle-based inclusive block scan (blockDim.x == 1024) ----------------
__device__ __forceinline__ int blockScanInc(int v, int* ws) {
    const unsigned FULL = 0xFFFFFFFFu;
    int lane = threadIdx.x & 31, w = threadIdx.x >> 5;
#pragma unroll
    for (int o = 1; o < 32; o <<= 1) {
        int n = __shfl_up_sync(FULL, v, o);
        if (lane >= o) v += n;
    }
    if (lane == 31) ws[w] = v;
    __syncthreads();
    if (w == 0) {
        int s = ws[lane];
#pragma unroll
        for (int o = 1; o < 32; o <<= 1) {
            int n = __shfl_up_sync(FULL, s, o);
            if (lane >= o) s += n;
        }
        ws[lane] = s;
    }
    __syncthreads();
    int r = v + ((w > 0) ? ws[w - 1] : 0);
    __syncthreads();
    return r;
}

// ---------------- K0: compact valid anchors + counting sort by x1 bin ----------------
__global__ __launch_bounds__(1024) void k0_sort(const float* __restrict__ cls,
                                                const float* __restrict__ boxes) {
    __shared__ int hist[XBINS];
    __shared__ int sstart[XBINS];
    __shared__ int ws[32];
    int c = blockIdx.x;
    int t = threadIdx.x;

    for (int b = t; b < XBINS; b += 1024) hist[b] = 0;
    __syncthreads();

    bool   myv[4];
    int    mybin[4];
    float4 mybox[4];
#pragma unroll
    for (int u = 0; u < 4; u++) {
        int a = t + u * 1024;
        float sc = cls[a * CC + c];
        myv[u] = sc > 0.5f;
        if (myv[u]) {
            mybox[u] = *(const float4*)(boxes + (size_t)a * (CC * 4) + c * 4);
            int b = __float2int_rd(mybox[u].x) + XOFF;
            b = max(0, min(XBINS - 1, b));
            mybin[u] = b;
            atomicAdd(&hist[b], 1);
        }
    }
    __syncthreads();

    int hv = (t < XBINS) ? hist[t] : 0;
    int inc = blockScanInc(hv, ws);
    if (t < XBINS) sstart[t] = inc - hv;
    if (t == XBINS - 1) g_m[c] = inc;
    __syncthreads();
    for (int b = t; b < XBINS; b += 1024) hist[b] = 0;
    __syncthreads();

#pragma unroll
    for (int u = 0; u < 4; u++) {
        if (myv[u]) {
            int a = t + u * 1024;
            int pos = sstart[mybin[u]] + atomicAdd(&hist[mybin[u]], 1);
            int slot = c * NN + pos;
            float4 b = mybox[u];
            g_sbox[slot] = b;
            g_saux[slot] = make_float2((b.z - b.x + 1.0f) * (b.w - b.y + 1.0f),
                                       __int_as_float(a));
            g_rmin[slot] = a;   // self hit baseline
        }
    }
}

// ---------------- K1: symmetric forward pair scan, 8 sub-threads per anchor ----------------
#define K1_TILE 64
#define K1_SUB 8
#define K1_THREADS 512
#define K1_SPAN 1024
__global__ __launch_bounds__(K1_THREADS) void k1_pairs() {
    __shared__ float4 tb[K1_SPAN];
    __shared__ float2 ta[K1_SPAN];

    int c  = blockIdx.x >> 6;           // 64 tiles per class
    int S0 = (blockIdx.x & 63) * K1_TILE;
    int m  = g_m[c];
    if (S0 >= m) return;

    for (int k = threadIdx.x; k < K1_SPAN; k += K1_THREADS) {
        int s = S0 + k;
        if (s < m) {
            tb[k] = g_sbox[c * NN + s];
            ta[k] = g_saux[c * NN + s];
        } else {
            tb[k] = make_float4(3.0e38f, 0.0f, -10.0f, -10.0f); // x1=+inf sentinel
            ta[k] = make_float2(1.0f, __int_as_float(0));
        }
    }
    __syncthreads();

    int ai  = threadIdx.x & (K1_TILE - 1);     // anchor within tile
    int sub = threadIdx.x >> 6;                // 0..7
    int s = S0 + ai;
    if (s >= m) return;

    float4 a    = tb[ai];
    float areaA = ta[ai].x;
    int   origI = __float_as_int(ta[ai].y);
    float limit = a.z + 2.0f;   // (x2_s + 1) + 1px bin-order slop

    for (int ts = ai + 1 + sub; ; ts += K1_SUB) {
        float4 b; float2 ax;
        if (ts < K1_SPAN) {
            b  = tb[ts];
            ax = ta[ts];
        } else {
            int gs = S0 + ts;
            if (gs >= m) break;
            b  = g_sbox[c * NN + gs];
            ax = g_saux[c * NN + gs];
        }
        if (b.x >= limit) break;

        float x1 = fmaxf(a.x, b.x);
        float y1 = fmaxf(a.y, b.y);
        float x2 = fminf(a.z, b.z);
        float y2 = fminf(a.w, b.w);
        float w = x2 - x1 + 1.0f;
        float h = y2 - y1 + 1.0f;
        float inter = w * h;
        float den = areaA + ax.x - inter;
        if (w > 0.0f && h > 0.0f && inter > 0.5f * den) {
            int origJ = __float_as_int(ax.y);
            atomicMin(&g_rmin[c * NN + s], origJ);
            atomicMin(&g_rmin[c * NN + S0 + ts], origI);
        }
    }
}

// ---------------- K2: fused values + scan + scatter + top-11 + survivor compaction ----------------
// dynamic smem layout: scnt[4096] | soff[4096] | cand[4096] (u64)
__global__ __launch_bounds__(1024) void k2_fused(const float* __restrict__ boxes,
                                                 const float* __restrict__ conf,
                                                 const float* __restrict__ poses,
                                                 const float* __restrict__ cls) {
    extern __shared__ int sm[];
    int* scnt = sm;                    // counts, later cursors
    int* soff = sm + NN;               // exclusive offsets
    unsigned long long* cand = (unsigned long long*)(sm + 2 * NN);
    __shared__ int ws[32];

    int c = blockIdx.x;
    int t = threadIdx.x;
    int m = g_m[c];

    *(int4*)&scnt[t * 4] = make_int4(0, 0, 0, 0);
    __syncthreads();

    // --- phase 1: per-slot winner value; count per target row (smem atomics) ---
    float vv[4];
    int   vi[4], vr[4];
    bool  has[4];
#pragma unroll
    for (int u = 0; u < 4; u++) {
        has[u] = false;
        int s = t + u * 1024;
        if (s < m) {
            int slot = c * NN + s;
            int r = g_rmin[slot];
            int i = __float_as_int(g_saux[slot].y);
            if (r != i) {
                float4 bi = g_sbox[slot];
                float4 br = *(const float4*)(boxes + (size_t)r * (CC * 4) + c * 4);
                float x1 = fmaxf(bi.x, br.x);
                float y1 = fmaxf(bi.y, br.y);
                float x2 = fminf(bi.z, br.z);
                float y2 = fminf(bi.w, br.w);
                float w = x2 - x1 + 1.0f;
                float h = y2 - y1 + 1.0f;
                float inter = w * h;
                float areaI = (bi.z - bi.x + 1.0f) * (bi.w - bi.y + 1.0f);
                float areaR = (br.z - br.x + 1.0f) * (br.w - br.y + 1.0f);
                float den = areaI + areaR - inter;
                float ov = (den == 0.0f) ? 0.0f : inter / den;
                if (w <= 0.0f || h <= 0.0f) ov = 0.0f;
                float v = (1.0f - ov) * conf[i * CC + c];
                if (v != 0.0f) {
                    vv[u] = v; vi[u] = i; vr[u] = r; has[u] = true;
                    atomicAdd(&scnt[r], 1);
                }
            }
        }
    }
    __syncthreads();

    // --- phase 2: exclusive scan over 4096 row counts ---
    int rcnt[4];
    int run = 0;
    int pre[4];
#pragma unroll
    for (int u = 0; u < 4; u++) {
        rcnt[u] = scnt[t * 4 + u];
        pre[u] = run;
        run += rcnt[u];
    }
    int incv = blockScanInc(run, ws);
    int base = incv - run;
#pragma unroll
    for (int u = 0; u < 4; u++) soff[t * 4 + u] = base + pre[u];
    __syncthreads();
    *(int4*)&scnt[t * 4] = make_int4(0, 0, 0, 0);
    __syncthreads();

    // --- phase 3: scatter candidates into smem CSR ---
#pragma unroll
    for (int u = 0; u < 4; u++) {
        if (has[u]) {
            int r = vr[u];
            int pos = soff[r] + atomicAdd(&scnt[r], 1);
            cand[pos] = ((unsigned long long)__float_as_uint(vv[u]) << 32) | (unsigned)vi[u];
        }
    }
    __syncthreads();

    // --- phase 4: per-row top-11 + averages ---
    int L = min(KH, m);
    bool survu[4];
#pragma unroll
    for (int u = 0; u < 4; u++) {
        int row = t * 4 + u;
        int cnt = rcnt[u];
        int used = 0;
        if (cnt > 0) {
            int off = soff[row];
            unsigned long long b[KH];
#pragma unroll
            for (int p = 0; p < KH; p++) b[p] = ~0ULL;
            for (int q = 0; q < cnt; q++) {
                unsigned long long x = cand[off + q];
#pragma unroll
                for (int p = 0; p < KH; p++) {
                    unsigned long long lo = (b[p] < x) ? b[p] : x;
                    unsigned long long hi = (b[p] < x) ? x : b[p];
                    b[p] = lo;
                    x = hi;
                }
            }
            used = min(min(cnt, KH), L);
            if (used > 0) {
                float ps[12], bs4[4];
#pragma unroll
                for (int d = 0; d < 12; d++) ps[d] = 0.0f;
#pragma unroll
                for (int d = 0; d < 4; d++) bs4[d] = 0.0f;
                for (int q = 0; q < used; q++) {
                    int a = (int)(b[q] & 0xFFFFFFFFu);
                    const float* pp = poses + (size_t)a * (CC * 12) + c * 12;
#pragma unroll
                    for (int d = 0; d < 12; d++) ps[d] += pp[d];
                    const float* bx = boxes + (size_t)a * (CC * 4) + c * 4;
#pragma unroll
                    for (int d = 0; d < 4; d++) bs4[d] += bx[d];
                }
                float den = (float)used;
                int grow = c * NN + row;
#pragma unroll
                for (int d = 0; d < 12; d++) g_pavg[grow * 12 + d] = ps[d] / den;
#pragma unroll
                for (int d = 0; d < 4; d++) g_bavg[grow * 4 + d] = bs4[d] / den;
            }
        }
        survu[u] = (used > 0);
    }
    __syncthreads();

    // --- phase 5: survivor compaction (rows ascending) + key build ---
    int srun = 0;
    int spre[4];
#pragma unroll
    for (int u = 0; u < 4; u++) {
        spre[u] = srun;
        srun += survu[u] ? 1 : 0;
    }
    int sinc = blockScanInc(srun, ws);
    int sbase = sinc - srun;
#pragma unroll
    for (int u = 0; u < 4; u++) {
        if (survu[u]) {
            int row = t * 4 + u;
            int pos = sbase + spre[u];
            g_srow[c * NN + pos] = row;
            unsigned ub = __float_as_uint(cls[row * CC + c]);
            g_skey[c * NN + pos] = ub ^ ((ub & 0x80000000u) ? 0xFFFFFFFFu : 0x80000000u);
        }
    }
    if (t == 1023) g_scount[c] = sinc;
}

// ---------------- K5: global top-100 over compacted survivors ----------------
__device__ __forceinline__ void find_thr(const int* hist, int nbins, int target,
                                         volatile int* out_b, volatile int* out_t,
                                         int* ws) {
    int t = threadIdx.x;
    if (t == 0) { *out_b = 0; *out_t = 0; }
    __syncthreads();
    if (nbins == 2048) {
        int b1 = 2047 - 2 * t;
        int b0 = b1 - 1;
        int h1 = hist[b1], h0 = hist[b0];
        int inc = blockScanInc(h1 + h0, ws);     // suffix sum at b0
        int suf0 = inc;
        int suf1 = inc - h0;
        if (suf1 >= target && suf1 - h1 < target) { *out_b = b1; *out_t = target - (suf1 - h1); }
        if (suf0 >= target && suf0 - h0 < target) { *out_b = b0; *out_t = target - (suf0 - h0); }
    } else {
        int b = 1023 - t;
        int h = hist[b];
        int inc = blockScanInc(h, ws);
        if (inc >= target && inc - h < target) { *out_b = b; *out_t = target - (inc - h); }
    }
    __syncthreads();
}

__global__ __launch_bounds__(1024) void k5_final(float* __restrict__ out, int out_size) {
    __shared__ int hist[2048];
    __shared__ int ws[32];
    __shared__ int cb[CC + 1];
    __shared__ int sel[MAXDET];
    __shared__ unsigned arr[MAXDET];
    __shared__ unsigned srt[MAXDET];
    __shared__ volatile int b_sh, t_sh;
    __shared__ int t1_sh, b1_sh, e_sh, gcnt, ecnt;
    __shared__ unsigned pre_sh, K100_sh;

    int t = threadIdx.x;
    if (t == 0) {
        int s = 0;
        for (int c = 0; c < CC; c++) { cb[c] = s; s += g_scount[c]; }
        cb[CC] = s;
        gcnt = 0; ecnt = 0;
    }
    __syncthreads();
    int S = cb[CC];

    // sel[q] = flat id of q-th survivor (class-major, rows ascending)
    if (t < MAXDET && t < S) {
        int c = 0;
        while (c < CC - 1 && t >= cb[c + 1]) c++;
        sel[t] = c * NN + g_srow[c * NN + (t - cb[c])];
    }

    // ---- radix-select level 1 (top 11 bits) ----
    hist[t] = 0; hist[t + 1024] = 0;
    __syncthreads();
    for (int q = t; q < S; q += 1024) {
        int c = 0;
        while (c < CC - 1 && q >= cb[c + 1]) c++;
        unsigned k = g_skey[c * NN + (q - cb[c])];
        atomicAdd(&hist[k >> 21], 1);
    }
    __syncthreads();
    find_thr(hist, 2048, MAXDET, &b_sh, &t_sh, ws);
    if (t == 0) { b1_sh = b_sh; t1_sh = t_sh; }
    __syncthreads();
    unsigned b1 = (unsigned)b1_sh;
    int tgt2 = t1_sh;

    // ---- level 2 (next 11 bits) ----
    hist[t] = 0; hist[t + 1024] = 0;
    __syncthreads();
    for (int q = t; q < S; q += 1024) {
        int c = 0;
        while (c < CC - 1 && q >= cb[c + 1]) c++;
        unsigned k = g_skey[c * NN + (q - cb[c])];
        if ((k >> 21) == b1) atomicAdd(&hist[(k >> 10) & 2047u], 1);
    }
    __syncthreads();
    find_thr(hist, 2048, tgt2, &b_sh, &t_sh, ws);
    if (t == 0) { pre_sh = (b1 << 11) | (unsigned)b_sh; e_sh = t_sh; }
    __syncthreads();
    unsigned pre = pre_sh;
    int tgt3 = e_sh;

    // ---- level 3 (low 10 bits) ----
    hist[t] = 0; hist[t + 1024] = 0;
    __syncthreads();
    for (int q = t; q < S; q += 1024) {
        int c = 0;
        while (c < CC - 1 && q >= cb[c + 1]) c++;
        unsigned k = g_skey[c * NN + (q - cb[c])];
        if ((k >> 10) == pre) atomicAdd(&hist[k & 1023u], 1);
    }
    __syncthreads();
    find_thr(hist, 1024, tgt3, &b_sh, &t_sh, ws);
    if (t == 0) { K100_sh = (pre << 10) | (unsigned)b_sh; e_sh = t_sh; }
    __syncthreads();
    unsigned K100 = K100_sh;
    int e = e_sh;
    int g = MAXDET - e;

    // ---- collect exactly 100 keys ----
    for (int q = t; q < S; q += 1024) {
        int c = 0;
        while (c < CC - 1 && q >= cb[c + 1]) c++;
        unsigned k = g_skey[c * NN + (q - cb[c])];
        if (k > K100) {
            int p = atomicAdd(&gcnt, 1);
            if (p < g) arr[p] = k;
        } else if (k == K100) {
            int p = atomicAdd(&ecnt, 1);
            if (p < e) arr[g + p] = k;
        }
    }
    __syncthreads();

    // ---- rank sort 100 keys descending ----
    int Smin = (S < MAXDET) ? S : MAXDET;
    if (t < Smin) {
        unsigned kt = arr[t];
        int r = 0;
        for (int j = 0; j < Smin; j++) {
            unsigned kj = arr[j];
            r += ((kj > kt) || (kj == kt && j < t)) ? 1 : 0;
        }
        srt[r] = kt;
    }
    __syncthreads();

    // outputs: [scores 100][labels 100][poses 1200][idx 100][boxes 400] = 1900 floats
    if (t < MAXDET) {
        int q = t;
        float osc = -1.0f;
        if (q < S) {
            unsigned u = srt[q];
            u = (u & 0x80000000u) ? (u ^ 0x80000000u) : ~u;
            osc = __uint_as_float(u);
        }
        if (q < out_size) out[q] = osc;
        float lab = (q < S) ? (float)(sel[q] >> 12) : -1.0f;
        if (100 + q < out_size) out[100 + q] = lab;
        float idx = (q < S) ? (float)(sel[q] & (NN - 1)) : -1.0f;
        if (1400 + q < out_size) out[1400 + q] = idx;
    }
    for (int q = t; q < 1200; q += 1024) {
        int k = q / 12, d = q % 12;
        float v = (k < S) ? g_pavg[sel[k] * 12 + d] : -1.0f;
        if (200 + q < out_size) out[200 + q] = v;
    }
    for (int q = t; q < 400; q += 1024) {
        int k = q >> 2, d = q & 3;
        float v = (k < S) ? g_bavg[sel[k] * 4 + d] : -1.0f;
        if (1500 + q < out_size) out[1500 + q] = v;
    }
}

// ---------------- launcher ----------------
extern "C" void kernel_launch(void* const* d_in, const int* in_sizes, int n_in,
                              void* d_out, int out_size) {
    (void)in_sizes; (void)n_in;
    const float* boxes = (const float*)d_in[1];
    const float* cls   = (const float*)d_in[2];
    const float* poses = (const float*)d_in[3];
    const float* conf  = (const float*)d_in[4];
    float* out = (float*)d_out;

    int smem2 = 2 * NN * (int)sizeof(int) + NN * (int)sizeof(unsigned long long) + 128;
    cudaFuncSetAttribute(k2_fused, cudaFuncAttributeMaxDynamicSharedMemorySize, smem2);

    k0_sort<<<CC, 1024>>>(cls, boxes);
    k1_pairs<<<CC * 64, K1_THREADS>>>();
    k2_fused<<<CC, 1024, smem2>>>(boxes, conf, poses, cls);
    k5_final<<<1, 1024>>>(out, out_size);
}

// round 7
// speedup vs baseline: 6.4553x; 1.0413x over previous
#include <cuda_runtime.h>

#define CC 8
#define NN 4096
#define NC (CC*NN)
#define KH 11
#define MAXDET 100
#define XBINS 768          // x1 in [-64, 704), 1px bins
#define XOFF 64

// ---------------- scratch (device globals; no allocation) ----------------
__device__ int    g_m[CC];            // valid count per class
__device__ float4 g_sbox[NC];         // bin-sorted boxes (by slot)
__device__ float2 g_saux[NC];         // sorted aux: (area, orig idx as int bits)
__device__ int    g_rmin[NC];         // per sorted slot: min orig idx of hit (init self)
__device__ float  g_pavg[NC*12];
__device__ float  g_bavg[NC*4];
__device__ int    g_scount[CC];       // survivors per class
__device__ int    g_srow[NC];         // compacted survivor rows (ascending per class)
__device__ unsigned g_skey[NC];       // compacted survivor keys (monotone score bits)
__device__ int    g_sync;             // last-block-done counter (reset by k0)

// ---------------- shuffle-based inclusive block scan (blockDim.x == 1024) ----------------
__device__ __forceinline__ int blockScanInc(int v, int* ws) {
    const unsigned FULL = 0xFFFFFFFFu;
    int lane = threadIdx.x & 31, w = threadIdx.x >> 5;
#pragma unroll
    for (int o = 1; o < 32; o <<= 1) {
        int n = __shfl_up_sync(FULL, v, o);
        if (lane >= o) v += n;
    }
    if (lane == 31) ws[w] = v;
    __syncthreads();
    if (w == 0) {
        int s = ws[lane];
#pragma unroll
        for (int o = 1; o < 32; o <<= 1) {
            int n = __shfl_up_sync(FULL, s, o);
            if (lane >= o) s += n;
        }
        ws[lane] = s;
    }
    __syncthreads();
    int r = v + ((w > 0) ? ws[w - 1] : 0);
    __syncthreads();
    return r;
}

// ---------------- K0: compact valid anchors + counting sort by x1 bin ----------------
__global__ __launch_bounds__(1024) void k0_sort(const float* __restrict__ cls,
                                                const float* __restrict__ boxes) {
    __shared__ int hist[XBINS];
    __shared__ int sstart[XBINS];
    __shared__ int ws[32];
    int c = blockIdx.x;
    int t = threadIdx.x;

    if (c == 0 && t == 0) g_sync = 0;      // reset fusion counter each launch

    for (int b = t; b < XBINS; b += 1024) hist[b] = 0;
    __syncthreads();

    bool   myv[4];
    int    mybin[4];
    float4 mybox[4];
#pragma unroll
    for (int u = 0; u < 4; u++) {
        int a = t + u * 1024;
        float sc = cls[a * CC + c];
        myv[u] = sc > 0.5f;
        if (myv[u]) {
            mybox[u] = *(const float4*)(boxes + (size_t)a * (CC * 4) + c * 4);
            int b = __float2int_rd(mybox[u].x) + XOFF;
            b = max(0, min(XBINS - 1, b));
            mybin[u] = b;
            atomicAdd(&hist[b], 1);
        }
    }
    __syncthreads();

    int hv = (t < XBINS) ? hist[t] : 0;
    int inc = blockScanInc(hv, ws);
    if (t < XBINS) sstart[t] = inc - hv;
    if (t == XBINS - 1) g_m[c] = inc;
    __syncthreads();
    for (int b = t; b < XBINS; b += 1024) hist[b] = 0;
    __syncthreads();

#pragma unroll
    for (int u = 0; u < 4; u++) {
        if (myv[u]) {
            int a = t + u * 1024;
            int pos = sstart[mybin[u]] + atomicAdd(&hist[mybin[u]], 1);
            int slot = c * NN + pos;
            float4 b = mybox[u];
            g_sbox[slot] = b;
            g_saux[slot] = make_float2((b.z - b.x + 1.0f) * (b.w - b.y + 1.0f),
                                       __int_as_float(a));
            g_rmin[slot] = a;   // self hit baseline
        }
    }
}

// ---------------- K1: symmetric forward pair scan, 16 sub-threads per anchor ----------------
#define K1_TILE 32
#define K1_SUB 16
#define K1_THREADS 512
#define K1_SPAN 1024
__global__ __launch_bounds__(K1_THREADS) void k1_pairs() {
    __shared__ float4 tb[K1_SPAN];
    __shared__ float2 ta[K1_SPAN];

    int c  = blockIdx.x >> 7;           // 128 tiles per class
    int S0 = (blockIdx.x & 127) * K1_TILE;
    int m  = g_m[c];
    if (S0 >= m) return;

    for (int k = threadIdx.x; k < K1_SPAN; k += K1_THREADS) {
        int s = S0 + k;
        if (s < m) {
            tb[k] = g_sbox[c * NN + s];
            ta[k] = g_saux[c * NN + s];
        } else {
            tb[k] = make_float4(3.0e38f, 0.0f, -10.0f, -10.0f); // x1=+inf sentinel
            ta[k] = make_float2(1.0f, __int_as_float(0));
        }
    }
    __syncthreads();

    int ai  = threadIdx.x & (K1_TILE - 1);     // anchor within tile
    int sub = threadIdx.x >> 5;                // 0..15
    int s = S0 + ai;
    if (s >= m) return;

    float4 a    = tb[ai];
    float areaA = ta[ai].x;
    int   origI = __float_as_int(ta[ai].y);
    float limit = a.z + 2.0f;   // (x2_s + 1) + 1px bin-order slop

    for (int ts = ai + 1 + sub; ; ts += K1_SUB) {
        float4 b; float2 ax;
        if (ts < K1_SPAN) {
            b  = tb[ts];
            ax = ta[ts];
        } else {
            int gs = S0 + ts;
            if (gs >= m) break;
            b  = g_sbox[c * NN + gs];
            ax = g_saux[c * NN + gs];
        }
        if (b.x >= limit) break;

        float x1 = fmaxf(a.x, b.x);
        float y1 = fmaxf(a.y, b.y);
        float x2 = fminf(a.z, b.z);
        float y2 = fminf(a.w, b.w);
        float w = x2 - x1 + 1.0f;
        float h = y2 - y1 + 1.0f;
        float inter = w * h;
        float den = areaA + ax.x - inter;
        if (w > 0.0f && h > 0.0f && inter > 0.5f * den) {
            int origJ = __float_as_int(ax.y);
            atomicMin(&g_rmin[c * NN + s], origJ);
            atomicMin(&g_rmin[c * NN + S0 + ts], origI);
        }
    }
}

// ---------------- k5 body: global top-100 over compacted survivors (one block) ----------------
__device__ __forceinline__ void find_thr(const int* hist, int nbins, int target,
                                         volatile int* out_b, volatile int* out_t,
                                         int* ws) {
    int t = threadIdx.x;
    if (t == 0) { *out_b = 0; *out_t = 0; }
    __syncthreads();
    if (nbins == 2048) {
        int b1 = 2047 - 2 * t;
        int b0 = b1 - 1;
        int h1 = hist[b1], h0 = hist[b0];
        int inc = blockScanInc(h1 + h0, ws);     // suffix sum at b0
        int suf0 = inc;
        int suf1 = inc - h0;
        if (suf1 >= target && suf1 - h1 < target) { *out_b = b1; *out_t = target - (suf1 - h1); }
        if (suf0 >= target && suf0 - h0 < target) { *out_b = b0; *out_t = target - (suf0 - h0); }
    } else {
        int b = 1023 - t;
        int h = hist[b];
        int inc = blockScanInc(h, ws);
        if (inc >= target && inc - h < target) { *out_b = b; *out_t = target - (inc - h); }
    }
    __syncthreads();
}

__device__ void k5_body(int* hist, int* ws, float* __restrict__ out, int out_size) {
    __shared__ int cb[CC + 1];
    __shared__ int sel[MAXDET];
    __shared__ unsigned arr[MAXDET];
    __shared__ unsigned srt[MAXDET];
    __shared__ volatile int b_sh, t_sh;
    __shared__ int t1_sh, b1_sh, e_sh, gcnt, ecnt;
    __shared__ unsigned pre_sh, K100_sh;

    int t = threadIdx.x;
    if (t == 0) {
        int s = 0;
        for (int c = 0; c < CC; c++) { cb[c] = s; s += g_scount[c]; }
        cb[CC] = s;
        gcnt = 0; ecnt = 0;
    }
    __syncthreads();
    int S = cb[CC];

    // sel[q] = flat id of q-th survivor (class-major, rows ascending)
    if (t < MAXDET && t < S) {
        int c = 0;
        while (c < CC - 1 && t >= cb[c + 1]) c++;
        sel[t] = c * NN + g_srow[c * NN + (t - cb[c])];
    }

    // ---- load this thread's keys ONCE (class-contiguous, no per-item search) ----
    unsigned kk[32];
    int nk = 0;
#pragma unroll 1
    for (int c = 0; c < CC; c++) {
        int cnt = cb[c + 1] - cb[c];
        for (int q = t; q < cnt; q += 1024) kk[nk++] = g_skey[c * NN + q];
    }

    // ---- radix-select level 1 (top 11 bits) ----
    hist[t] = 0; hist[t + 1024] = 0;
    __syncthreads();
    for (int i = 0; i < nk; i++) atomicAdd(&hist[kk[i] >> 21], 1);
    __syncthreads();
    find_thr(hist, 2048, MAXDET, &b_sh, &t_sh, ws);
    if (t == 0) { b1_sh = b_sh; t1_sh = t_sh; }
    __syncthreads();
    unsigned b1 = (unsigned)b1_sh;
    int tgt2 = t1_sh;

    // ---- level 2 (next 11 bits) ----
    hist[t] = 0; hist[t + 1024] = 0;
    __syncthreads();
    for (int i = 0; i < nk; i++)
        if ((kk[i] >> 21) == b1) atomicAdd(&hist[(kk[i] >> 10) & 2047u], 1);
    __syncthreads();
    find_thr(hist, 2048, tgt2, &b_sh, &t_sh, ws);
    if (t == 0) { pre_sh = (b1 << 11) | (unsigned)b_sh; e_sh = t_sh; }
    __syncthreads();
    unsigned pre = pre_sh;
    int tgt3 = e_sh;

    // ---- level 3 (low 10 bits) ----
    hist[t] = 0; hist[t + 1024] = 0;
    __syncthreads();
    for (int i = 0; i < nk; i++)
        if ((kk[i] >> 10) == pre) atomicAdd(&hist[kk[i] & 1023u], 1);
    __syncthreads();
    find_thr(hist, 1024, tgt3, &b_sh, &t_sh, ws);
    if (t == 0) { K100_sh = (pre << 10) | (unsigned)b_sh; e_sh = t_sh; }
    __syncthreads();
    unsigned K100 = K100_sh;
    int e = e_sh;
    int g = MAXDET - e;

    // ---- collect exactly 100 keys ----
    for (int i = 0; i < nk; i++) {
        unsigned k = kk[i];
        if (k > K100) {
            int p = atomicAdd(&gcnt, 1);
            if (p < g) arr[p] = k;
        } else if (k == K100) {
            int p = atomicAdd(&ecnt, 1);
            if (p < e) arr[g + p] = k;
        }
    }
    __syncthreads();

    // ---- rank sort 100 keys descending ----
    int Smin = (S < MAXDET) ? S : MAXDET;
    if (t < Smin) {
        unsigned kt = arr[t];
        int r = 0;
        for (int j = 0; j < Smin; j++) {
            unsigned kj = arr[j];
            r += ((kj > kt) || (kj == kt && j < t)) ? 1 : 0;
        }
        srt[r] = kt;
    }
    __syncthreads();

    // outputs: [scores 100][labels 100][poses 1200][idx 100][boxes 400] = 1900 floats
    if (t < MAXDET) {
        int q = t;
        float osc = -1.0f;
        if (q < S) {
            unsigned u = srt[q];
            u = (u & 0x80000000u) ? (u ^ 0x80000000u) : ~u;
            osc = __uint_as_float(u);
        }
        if (q < out_size) out[q] = osc;
        float lab = (q < S) ? (float)(sel[q] >> 12) : -1.0f;
        if (100 + q < out_size) out[100 + q] = lab;
        float idx = (q < S) ? (float)(sel[q] & (NN - 1)) : -1.0f;
        if (1400 + q < out_size) out[1400 + q] = idx;
    }
    for (int q = t; q < 1200; q += 1024) {
        int k = q / 12, d = q % 12;
        float v = (k < S) ? g_pavg[sel[k] * 12 + d] : -1.0f;
        if (200 + q < out_size) out[200 + q] = v;
    }
    for (int q = t; q < 400; q += 1024) {
        int k = q >> 2, d = q & 3;
        float v = (k < S) ? g_bavg[sel[k] * 4 + d] : -1.0f;
        if (1500 + q < out_size) out[1500 + q] = v;
    }
}

// ---------------- K2: fused values+scan+scatter+top-11+compaction, last block runs k5 ----------------
// dynamic smem layout: scnt[4096] | soff[4096] | cand[4096] (u64)
__global__ __launch_bounds__(1024) void k2_fused(const float* __restrict__ boxes,
                                                 const float* __restrict__ conf,
                                                 const float* __restrict__ poses,
                                                 const float* __restrict__ cls,
                                                 float* __restrict__ out, int out_size) {
    extern __shared__ int sm[];
    int* scnt = sm;                    // counts, later cursors
    int* soff = sm + NN;               // exclusive offsets
    unsigned long long* cand = (unsigned long long*)(sm + 2 * NN);
    __shared__ int ws[32];
    __shared__ int is_last;

    int c = blockIdx.x;
    int t = threadIdx.x;
    int m = g_m[c];

    *(int4*)&scnt[t * 4] = make_int4(0, 0, 0, 0);
    __syncthreads();

    // --- phase 1: per-slot winner value; count per target row (smem atomics) ---
    float vv[4];
    int   vi[4], vr[4];
    bool  has[4];
#pragma unroll
    for (int u = 0; u < 4; u++) {
        has[u] = false;
        int s = t + u * 1024;
        if (s < m) {
            int slot = c * NN + s;
            int r = g_rmin[slot];
            int i = __float_as_int(g_saux[slot].y);
            if (r != i) {
                float4 bi = g_sbox[slot];
                float4 br = *(const float4*)(boxes + (size_t)r * (CC * 4) + c * 4);
                float x1 = fmaxf(bi.x, br.x);
                float y1 = fmaxf(bi.y, br.y);
                float x2 = fminf(bi.z, br.z);
                float y2 = fminf(bi.w, br.w);
                float w = x2 - x1 + 1.0f;
                float h = y2 - y1 + 1.0f;
                float inter = w * h;
                float areaI = (bi.z - bi.x + 1.0f) * (bi.w - bi.y + 1.0f);
                float areaR = (br.z - br.x + 1.0f) * (br.w - br.y + 1.0f);
                float den = areaI + areaR - inter;
                float ov = (den == 0.0f) ? 0.0f : inter / den;
                if (w <= 0.0f || h <= 0.0f) ov = 0.0f;
                float v = (1.0f - ov) * conf[i * CC + c];
                if (v != 0.0f) {
                    vv[u] = v; vi[u] = i; vr[u] = r; has[u] = true;
                    atomicAdd(&scnt[r], 1);
                }
            }
        }
    }
    __syncthreads();

    // --- phase 2: exclusive scan over 4096 row counts ---
    int rcnt[4];
    int run = 0;
    int pre[4];
#pragma unroll
    for (int u = 0; u < 4; u++) {
        rcnt[u] = scnt[t * 4 + u];
        pre[u] = run;
        run += rcnt[u];
    }
    int incv = blockScanInc(run, ws);
    int base = incv - run;
#pragma unroll
    for (int u = 0; u < 4; u++) soff[t * 4 + u] = base + pre[u];
    __syncthreads();
    *(int4*)&scnt[t * 4] = make_int4(0, 0, 0, 0);
    __syncthreads();

    // --- phase 3: scatter candidates into smem CSR ---
#pragma unroll
    for (int u = 0; u < 4; u++) {
        if (has[u]) {
            int r = vr[u];
            int pos = soff[r] + atomicAdd(&scnt[r], 1);
            cand[pos] = ((unsigned long long)__float_as_uint(vv[u]) << 32) | (unsigned)vi[u];
        }
    }
    __syncthreads();

    // --- phase 4: per-row top-11 + averages ---
    int L = min(KH, m);
    bool survu[4];
#pragma unroll
    for (int u = 0; u < 4; u++) {
        int row = t * 4 + u;
        int cnt = rcnt[u];
        int used = 0;
        if (cnt > 0) {
            int off = soff[row];
            unsigned long long b[KH];
#pragma unroll
            for (int p = 0; p < KH; p++) b[p] = ~0ULL;
            for (int q = 0; q < cnt; q++) {
                unsigned long long x = cand[off + q];
#pragma unroll
                for (int p = 0; p < KH; p++) {
                    unsigned long long lo = (b[p] < x) ? b[p] : x;
                    unsigned long long hi = (b[p] < x) ? x : b[p];
                    b[p] = lo;
                    x = hi;
                }
            }
            used = min(min(cnt, KH), L);
            if (used > 0) {
                float ps[12], bs4[4];
#pragma unroll
                for (int d = 0; d < 12; d++) ps[d] = 0.0f;
#pragma unroll
                for (int d = 0; d < 4; d++) bs4[d] = 0.0f;
                for (int q = 0; q < used; q++) {
                    int a = (int)(b[q] & 0xFFFFFFFFu);
                    const float* pp = poses + (size_t)a * (CC * 12) + c * 12;
#pragma unroll
                    for (int d = 0; d < 12; d++) ps[d] += pp[d];
                    const float* bx = boxes + (size_t)a * (CC * 4) + c * 4;
#pragma unroll
                    for (int d = 0; d < 4; d++) bs4[d] += bx[d];
                }
                float den = (float)used;
                int grow = c * NN + row;
#pragma unroll
                for (int d = 0; d < 12; d++) g_pavg[grow * 12 + d] = ps[d] / den;
#pragma unroll
                for (int d = 0; d < 4; d++) g_bavg[grow * 4 + d] = bs4[d] / den;
            }
        }
        survu[u] = (used > 0);
    }
    __syncthreads();

    // --- phase 5: survivor compaction (rows ascending) + key build ---
    int srun = 0;
    int spre[4];
#pragma unroll
    for (int u = 0; u < 4; u++) {
        spre[u] = srun;
        srun += survu[u] ? 1 : 0;
    }
    int sinc = blockScanInc(srun, ws);
    int sbase = sinc - srun;
#pragma unroll
    for (int u = 0; u < 4; u++) {
        if (survu[u]) {
            int row = t * 4 + u;
            int pos = sbase + spre[u];
            g_srow[c * NN + pos] = row;
            unsigned ub = __float_as_uint(cls[row * CC + c]);
            g_skey[c * NN + pos] = ub ^ ((ub & 0x80000000u) ? 0xFFFFFFFFu : 0x80000000u);
        }
    }
    if (t == 1023) g_scount[c] = sinc;
    __syncthreads();

    // --- phase 6: last block runs global selection (threadFenceReduction pattern) ---
    if (t == 0) {
        __threadfence();
        int old = atomicAdd(&g_sync, 1);
        is_last = (old == CC - 1) ? 1 : 0;
    }
    __syncthreads();
    if (is_last) {
        k5_body(sm /* reuse as hist[2048] */, ws, out, out_size);
    }
}

// ---------------- launcher ----------------
extern "C" void kernel_launch(void* const* d_in, const int* in_sizes, int n_in,
                              void* d_out, int out_size) {
    (void)in_sizes; (void)n_in;
    const float* boxes = (const float*)d_in[1];
    const float* cls   = (const float*)d_in[2];
    const float* poses = (const float*)d_in[3];
    const float* conf  = (const float*)d_in[4];
    float* out = (float*)d_out;

    int smem2 = 2 * NN * (int)sizeof(int) + NN * (int)sizeof(unsigned long long) + 128;
    cudaFuncSetAttribute(k2_fused, cudaFuncAttributeMaxDynamicSharedMemorySize, smem2);

    k0_sort<<<CC, 1024>>>(cls, boxes);
    k1_pairs<<<CC * 128, K1_THREADS>>>();
    k2_fused<<<CC, 1024, smem2>>>(boxes, conf, poses, cls, out, out_size);
}